// round 13
// baseline (speedup 1.0000x reference)
#include <cuda_runtime.h>
#include <cuda_bf16.h>
#include <math.h>
#include <stdint.h>
#include <cstdint>

typedef unsigned long long ull;

constexpr int NNODE = 10000;
constexpr int NEDGE = 160000;
constexpr int C = 32;
constexpr int H = 64;
constexpr int F_OFF1 = NNODE * C;
constexpr int F_OFF2 = 4 * NNODE * C;
constexpr int F_OFF3 = 9 * NNODE * C;
constexpr int FTOT   = 16 * NNODE * C;

// ---------------- scratch ---------------------------------------------------
__device__ __align__(16) __nv_bfloat16 g_hb_hi[(size_t)NEDGE * H];
__device__ __align__(16) __nv_bfloat16 g_hb_lo[(size_t)NEDGE * H];
__device__ __align__(16) __nv_bfloat16 g_wb_hi[512 * 64];
__device__ __align__(16) __nv_bfloat16 g_wb_lo[512 * 64];
__device__ __align__(16) __nv_bfloat16 g_w1b_hi[64 * 128];
__device__ __align__(16) __nv_bfloat16 g_w1b_lo[64 * 128];
__device__ float  g_w [(size_t)NEDGE * 384];   // original edge order
__device__ float  g_ew[(size_t)NEDGE * 128];   // original edge order
__device__ float  g_sh[(size_t)NEDGE * 16];    // original edge order
__device__ float2 g_geo[NEDGE];                // original edge order
__device__ float  g_f[2][FTOT];
__device__ float  g_agg[FTOT];
__device__ float  g_gate[NNODE * C];
__device__ int    g_cnt[NNODE];
__device__ int    g_fill[NNODE];
__device__ int    g_rowstart[NNODE + 1];
__device__ int    g_eid[NEDGE];                // CSR: sorted pos -> original edge id

__device__ __forceinline__ float siluf(float x) { return x / (1.0f + expf(-x)); }

__device__ __forceinline__ ull dup2(float a) {
    ull r;
    asm("mov.b64 %0, {%1, %1};" : "=l"(r) : "r"(__float_as_uint(a)));
    return r;
}
__device__ __forceinline__ void ffma2(ull& d, ull a, ull b) {
    asm("fma.rn.f32x2 %0, %1, %2, %0;" : "+l"(d) : "l"(a), "l"(b));
}
__device__ __forceinline__ float2 unpack2(ull v) {
    float2 f;
    asm("mov.b64 {%0, %1}, %2;" : "=f"(f.x), "=f"(f.y) : "l"(v));
    return f;
}
__device__ __forceinline__ uint32_t bf2u(__nv_bfloat162 v) {
    union { __nv_bfloat162 b; uint32_t u; } c;
    c.b = v;
    return c.u;
}
__device__ __forceinline__ uint32_t smem_u32(const void* p) {
    uint32_t a;
    asm("{ .reg .u64 t; cvta.to.shared.u64 t, %1; cvt.u32.u64 %0, t; }" : "=r"(a) : "l"(p));
    return a;
}
#define SWZ128(o) ((o) ^ (((o) >> 3) & 0x70))

__device__ __forceinline__ void ldm_x4(uint32_t* r, uint32_t addr) {
    asm volatile("ldmatrix.sync.aligned.m8n8.x4.shared.b16 {%0,%1,%2,%3}, [%4];"
                 : "=r"(r[0]), "=r"(r[1]), "=r"(r[2]), "=r"(r[3]) : "r"(addr));
}
__device__ __forceinline__ void mma16816(float* c, const uint32_t* a,
                                         uint32_t b0, uint32_t b1) {
    asm volatile(
        "mma.sync.aligned.m16n8k16.row.col.f32.bf16.bf16.f32 "
        "{%0,%1,%2,%3}, {%4,%5,%6,%7}, {%8,%9}, {%0,%1,%2,%3};"
        : "+f"(c[0]), "+f"(c[1]), "+f"(c[2]), "+f"(c[3])
        : "r"(a[0]), "r"(a[1]), "r"(a[2]), "r"(a[3]), "r"(b0), "r"(b1));
}

// ---------------- K0: per-edge geometry + SH (original order) --------------
__global__ void k_geom(const float* __restrict__ pos, const int* __restrict__ ei) {
    int e = blockIdx.x * 256 + threadIdx.x;
    int s = ei[e], d = ei[NEDGE + e];
    float ax = pos[3 * s], ay = pos[3 * s + 1], az = pos[3 * s + 2];
    float bx = pos[3 * d], by = pos[3 * d + 1], bz = pos[3 * d + 2];
    float vx = bx - ax, vy = by - ay, vz = bz - az;
    float r = sqrtf(vx * vx + vy * vy + vz * vz + 1e-12f);
    float u = fminf(r * (1.0f / 5.0f), 1.0f);
    float env = 0.5f * (cospif(u) + 1.0f);
    g_geo[e] = make_float2(u, env * 0.63245553203f / r);
    float inv = 1.0f / r;
    float x = vx * inv, y = vy * inv, z = vz * inv;
    float x2 = x * x, y2 = y * y, z2 = z * z;
    float4* shp = reinterpret_cast<float4*>(g_sh + (size_t)e * 16);
    shp[0] = make_float4(1.0f, 1.7320508f * x, 1.7320508f * y, 1.7320508f * z);
    shp[1] = make_float4(3.87298335f * x * y, 3.87298335f * y * z,
                         1.11803399f * (3.0f * z2 - 1.0f), 3.87298335f * x * z);
    shp[2] = make_float4(1.93649167f * (x2 - y2),
                         2.09165007f * y * (3.0f * x2 - y2),
                         10.2469508f * x * y * z,
                         1.62018517f * y * (5.0f * z2 - 1.0f));
    shp[3] = make_float4(1.32287566f * (5.0f * z2 * z - 3.0f * z),
                         1.62018517f * x * (5.0f * z2 - 1.0f),
                         5.12347538f * z * (x2 - y2),
                         2.09165007f * x * (x2 - 3.0f * y2));
}

// ---------------- weight pre-convert ---------------------------------------
__global__ void k_wconv(const float* __restrict__ rw2,
                        const float* __restrict__ edge_w,
                        const float* __restrict__ rw1) {
    int idx = blockIdx.x * 256 + threadIdx.x;
    if (idx < 512 * 64) {
        int n = idx >> 6, k = idx & 63;
        float x = (n < 384) ? rw2[k * 384 + n] : edge_w[k * 128 + n - 384];
        __nv_bfloat16 h = __float2bfloat16_rn(x);
        g_wb_hi[idx] = h;
        g_wb_lo[idx] = __float2bfloat16_rn(x - __bfloat162float(h));
    } else {
        int j = idx - 512 * 64;
        int n = j >> 7, k = j & 127;
        float x = rw1[k * 64 + n];
        __nv_bfloat16 h = __float2bfloat16_rn(x);
        g_w1b_hi[j] = h;
        g_w1b_lo[j] = __float2bfloat16_rn(x - __bfloat162float(h));
    }
}

// ---------------- K2: h = silu(rb @ rw1 + rb1) via HMMA bf16x3 -------------
constexpr int G1_A0H = 0;
constexpr int G1_A1H = 16384;
constexpr int G1_A0L = 32768;
constexpr int G1_A1L = 49152;
constexpr int G1_B0H = 65536;
constexpr int G1_B0L = 81920;
constexpr int G1_TOT = 98304;
__global__ __launch_bounds__(256) void k_gemm1hmma(const float* __restrict__ rb1) {
    extern __shared__ char smem[];
    uint32_t sb = smem_u32(smem);
    int tid = threadIdx.x, wid = tid >> 5, lane = tid & 31;
    int e0 = blockIdx.x * 128;

    for (int idx = tid; idx < 1024; idx += 256) {
        int row = idx >> 4, ch = idx & 15;
        int toff = (ch < 8) ? 0 : 8192;
        uint32_t off = SWZ128((uint32_t)(row * 128 + (ch & 7) * 16));
        size_t gsrc = (size_t)row * 128 + ch * 8;
        *reinterpret_cast<uint4*>(smem + G1_B0H + toff + off) =
            *reinterpret_cast<const uint4*>(&g_w1b_hi[gsrc]);
        *reinterpret_cast<uint4*>(smem + G1_B0L + toff + off) =
            *reinterpret_cast<const uint4*>(&g_w1b_lo[gsrc]);
    }
    {
        int row = tid & 127, half = tid >> 7;
        float2 gg = g_geo[e0 + row];
        float s1, c1;
        sincospif(gg.x, &s1, &c1);
        float two = 2.0f * c1;
        char* tH = smem + (half ? G1_A1H : G1_A0H);
        char* tL = smem + (half ? G1_A1L : G1_A0L);
#pragma unroll
        for (int seg = 0; seg < 2; seg++) {
            int n0 = half * 64 + seg * 32 + 1;
            float sa, ca;
            sincospif((float)n0 * gg.x, &sa, &ca);
            float sbv = sa * c1 + ca * s1;
#pragma unroll
            for (int i = 0; i < 32; i += 2) {
                float v0 = gg.y * sa;
                float sn = fmaf(two, sbv, -sa); sa = sbv; sbv = sn;
                float v1 = gg.y * sa;
                sn = fmaf(two, sbv, -sa); sa = sbv; sbv = sn;
                __nv_bfloat162 h = __float22bfloat162_rn(make_float2(v0, v1));
                float2 hf = __bfloat1622float2(h);
                __nv_bfloat162 l = __float22bfloat162_rn(make_float2(v0 - hf.x, v1 - hf.y));
                uint32_t off = SWZ128((uint32_t)(row * 128 + (seg * 32 + i) * 2));
                *reinterpret_cast<uint32_t*>(tH + off) = bf2u(h);
                *reinterpret_cast<uint32_t*>(tL + off) = bf2u(l);
            }
        }
    }
    __syncthreads();

    int wr = wid & 3, wc = wid >> 2;
    int rowA0 = wr * 32 + (lane & 7) + ((lane >> 3) & 1) * 8;
    int kcA   = (lane >> 4) * 16;
    int rowB0 = wc * 32 + (lane & 7) + ((lane >> 4) & 1) * 8;
    int kcB   = ((lane >> 3) & 1) * 16;

    float acc[2][4][4];
#pragma unroll
    for (int i = 0; i < 2; i++)
#pragma unroll
        for (int j = 0; j < 4; j++)
#pragma unroll
            for (int q = 0; q < 4; q++) acc[i][j][q] = 0.0f;

    const uint32_t A_hi[2] = {sb + G1_A0H, sb + G1_A1H};
    const uint32_t A_lo[2] = {sb + G1_A0L, sb + G1_A1L};
    const uint32_t B_hi[2] = {sb + G1_B0H, sb + G1_B0H + 8192};
    const uint32_t B_lo[2] = {sb + G1_B0L, sb + G1_B0L + 8192};
#pragma unroll
    for (int p = 0; p < 3; p++) {
        const uint32_t* Ab = (p == 2) ? A_lo : A_hi;
        const uint32_t* Bb = (p == 1) ? B_lo : B_hi;
#pragma unroll
        for (int ks = 0; ks < 8; ks++) {
            int kh = ks >> 2, ksl = ks & 3;
            uint32_t a[2][4];
#pragma unroll
            for (int rt = 0; rt < 2; rt++) {
                uint32_t boff = (uint32_t)((rowA0 + rt * 16) * 128 + ksl * 32 + kcA);
                ldm_x4(a[rt], Ab[kh] + SWZ128(boff));
            }
#pragma unroll
            for (int ct2 = 0; ct2 < 2; ct2++) {
                uint32_t b[4];
                uint32_t boff = (uint32_t)((rowB0 + ct2 * 16) * 128 + ksl * 32 + kcB);
                ldm_x4(b, Bb[kh] + SWZ128(boff));
#pragma unroll
                for (int rt = 0; rt < 2; rt++) {
                    mma16816(acc[rt][2 * ct2],     a[rt], b[0], b[1]);
                    mma16816(acc[rt][2 * ct2 + 1], a[rt], b[2], b[3]);
                }
            }
        }
    }

    int lg = lane >> 2, lc = (lane & 3) * 2;
#pragma unroll
    for (int rt = 0; rt < 2; rt++) {
#pragma unroll
        for (int ct = 0; ct < 4; ct++) {
            int col = wc * 32 + ct * 8 + lc;
            float2 bv = *reinterpret_cast<const float2*>(&rb1[col]);
            int row0 = e0 + wr * 32 + rt * 16 + lg;
#pragma unroll
            for (int half = 0; half < 2; half++) {
                int row = row0 + half * 8;
                float v0 = siluf(acc[rt][ct][2 * half]     + bv.x);
                float v1 = siluf(acc[rt][ct][2 * half + 1] + bv.y);
                __nv_bfloat162 h = __float22bfloat162_rn(make_float2(v0, v1));
                float2 hf = __bfloat1622float2(h);
                __nv_bfloat162 l = __float22bfloat162_rn(make_float2(v0 - hf.x, v1 - hf.y));
                size_t base = (size_t)row * 64 + col;
                *reinterpret_cast<uint32_t*>(&g_hb_hi[base]) = bf2u(h);
                *reinterpret_cast<uint32_t*>(&g_hb_lo[base]) = bf2u(l);
            }
        }
    }
}

// ---------------- K3: HMMA bf16x3 GEMM, 128x64 tile, 2 CTAs/SM -------------
// blockIdx.x = col block (0..7, 64 cols each over [w(384)|ew(128)]), .y = rows.
constexpr int S2_AH  = 0;
constexpr int S2_AL  = 16384;
constexpr int S2_BH  = 32768;     // 64 rows x 128B
constexpr int S2_BL  = 40960;
constexpr int S2_TOT = 49152;
__global__ __launch_bounds__(256, 2) void k_gemm2hmma(const float* __restrict__ rb2,
                                                      const float* __restrict__ edge_b) {
    extern __shared__ char smem[];
    uint32_t sb = smem_u32(smem);
    int tid = threadIdx.x;
    int wid = tid >> 5, lane = tid & 31;
    int jb = blockIdx.x;              // 64-col block
    int e0 = blockIdx.y * 128;
    int wr = wid & 3;                 // 4 row groups x 32
    int wc = wid >> 2;                // 2 col groups x 32

    // ---- fill: A 128rows x 32k bf16x2 (hi/lo), B 64rows x 32k ----
    for (int idx = tid; idx < 1024; idx += 256) {
        int row = idx >> 3, ch = idx & 7;
        uint32_t off = SWZ128((uint32_t)(row * 128 + ch * 16));
        size_t ga = (size_t)(e0 + row) * 64 + ch * 8;
        *reinterpret_cast<uint4*>(smem + S2_AH + off) =
            *reinterpret_cast<const uint4*>(&g_hb_hi[ga]);
        *reinterpret_cast<uint4*>(smem + S2_AL + off) =
            *reinterpret_cast<const uint4*>(&g_hb_lo[ga]);
    }
    for (int idx = tid; idx < 512; idx += 256) {
        int row = idx >> 3, ch = idx & 7;
        uint32_t off = SWZ128((uint32_t)(row * 128 + ch * 16));
        size_t gb = (size_t)(jb * 64 + row) * 64 + ch * 8;
        *reinterpret_cast<uint4*>(smem + S2_BH + off) =
            *reinterpret_cast<const uint4*>(&g_wb_hi[gb]);
        *reinterpret_cast<uint4*>(smem + S2_BL + off) =
            *reinterpret_cast<const uint4*>(&g_wb_lo[gb]);
    }
    __syncthreads();

    int rowA0 = wr * 32 + (lane & 7) + ((lane >> 3) & 1) * 8;
    int kcA   = (lane >> 4) * 16;
    int rowB0 = wc * 32 + (lane & 7) + ((lane >> 4) & 1) * 8;
    int kcB   = ((lane >> 3) & 1) * 16;

    float acc[2][4][4];
#pragma unroll
    for (int i = 0; i < 2; i++)
#pragma unroll
        for (int j = 0; j < 4; j++)
#pragma unroll
            for (int q = 0; q < 4; q++) acc[i][j][q] = 0.0f;

    const uint32_t Abase[3] = {sb + S2_AH, sb + S2_AH, sb + S2_AL};
    const uint32_t Bbase[3] = {sb + S2_BH, sb + S2_BL, sb + S2_BH};
#pragma unroll
    for (int p = 0; p < 3; p++) {
        uint32_t Ab = Abase[p], Bb = Bbase[p];
#pragma unroll
        for (int ks = 0; ks < 4; ks++) {
            uint32_t a[2][4];
#pragma unroll
            for (int rt = 0; rt < 2; rt++) {
                uint32_t boff = (uint32_t)((rowA0 + rt * 16) * 128 + ks * 32 + kcA);
                ldm_x4(a[rt], Ab + SWZ128(boff));
            }
#pragma unroll
            for (int ct2 = 0; ct2 < 2; ct2++) {
                uint32_t b[4];
                uint32_t boff = (uint32_t)((rowB0 + ct2 * 16) * 128 + ks * 32 + kcB);
                ldm_x4(b, Bb + SWZ128(boff));
#pragma unroll
                for (int rt = 0; rt < 2; rt++) {
                    mma16816(acc[rt][2 * ct2],     a[rt], b[0], b[1]);
                    mma16816(acc[rt][2 * ct2 + 1], a[rt], b[2], b[3]);
                }
            }
        }
    }

    // ---- epilogue: bias + direct float2 stores ----
    bool inw = jb < 6;
    const float* bias_base = inw ? (rb2 + jb * 64) : (edge_b + (jb - 6) * 64);
    int stride = inw ? 384 : 128;
    float* gbase = inw ? (g_w + jb * 64) : (g_ew + (jb - 6) * 64);
    int lg = lane >> 2;
    int lc = (lane & 3) * 2;
#pragma unroll
    for (int rt = 0; rt < 2; rt++) {
#pragma unroll
        for (int ct = 0; ct < 4; ct++) {
            int colg = wc * 32 + ct * 8 + lc;
            float2 bv = *reinterpret_cast<const float2*>(bias_base + colg);
            int row0 = e0 + wr * 32 + rt * 16 + lg;
            float* d0 = gbase + (size_t)row0 * stride + colg;
            float* d1 = gbase + (size_t)(row0 + 8) * stride + colg;
            *reinterpret_cast<float2*>(d0) =
                make_float2(acc[rt][ct][0] + bv.x, acc[rt][ct][1] + bv.y);
            *reinterpret_cast<float2*>(d1) =
                make_float2(acc[rt][ct][2] + bv.x, acc[rt][ct][3] + bv.y);
        }
    }
}

// ---------------- sorting: counting sort by dst (eid only) -----------------
__global__ void k_zero_sort() {
    int i = blockIdx.x * 256 + threadIdx.x;
    if (i < NNODE) { g_cnt[i] = 0; g_fill[i] = 0; }
}
__global__ void k_count(const int* __restrict__ ei) {
    int e = blockIdx.x * 256 + threadIdx.x;
    atomicAdd(&g_cnt[ei[NEDGE + e]], 1);
}
__global__ void k_scan() {
    __shared__ int part[1024];
    int t = threadIdx.x;
    int base = t * 10;
    int vals[10];
    int s = 0;
#pragma unroll
    for (int i = 0; i < 10; i++) {
        int idx = base + i;
        int v = (idx < NNODE) ? g_cnt[idx] : 0;
        vals[i] = s; s += v;
    }
    part[t] = s;
    __syncthreads();
    for (int d = 1; d < 1024; d <<= 1) {
        int v = (t >= d) ? part[t - d] : 0;
        __syncthreads();
        part[t] += v;
        __syncthreads();
    }
    int off = (t == 0) ? 0 : part[t - 1];
#pragma unroll
    for (int i = 0; i < 10; i++) {
        int idx = base + i;
        if (idx < NNODE) g_rowstart[idx] = off + vals[i];
    }
    if (t == 1023) g_rowstart[NNODE] = part[1023];
}
__global__ void k_filleid(const int* __restrict__ ei) {
    int e = blockIdx.x * 256 + threadIdx.x;
    int d = ei[NEDGE + e];
    int p = g_rowstart[d] + atomicAdd(&g_fill[d], 1);
    g_eid[p] = e;
}

// ---------------- init f[0] -------------------------------------------------
__global__ void k_initf(const float* __restrict__ node_embed,
                        const int* __restrict__ species) {
    int i4 = blockIdx.x * 256 + threadIdx.x;
    int idx = i4 * 4;
    float4 v;
    if (idx < NNODE * C) {
        int n = idx >> 5, c = idx & 31;
        v = *reinterpret_cast<const float4*>(&node_embed[(species[n] << 5) + c]);
    } else {
        v = make_float4(0.f, 0.f, 0.f, 0.f);
    }
    *reinterpret_cast<float4*>(&g_f[0][idx]) = v;
}

// ---------------- K4a: gather-aggregate + l0 update + gate -----------------
__global__ __launch_bounds__(256) void k_gather(const float* __restrict__ self_w,
                                                const float* __restrict__ msg_w,
                                                const float* __restrict__ gate_w,
                                                const int* __restrict__ ei,
                                                int t, int cur,
                                                float* __restrict__ out) {
    __shared__ float sS0[1024];
    __shared__ float sM0[1024];
    __shared__ float sGw[1024];
    int tid = threadIdx.x;
    for (int i = tid; i < 1024; i += 256) {
        sS0[i] = self_w[t * 4096 + i];
        sM0[i] = msg_w[t * 4096 + i];
        sGw[i] = gate_w[t * 1024 + i];
    }
    __syncthreads();
    int lane = tid & 31;
    int n = blockIdx.x * 8 + (tid >> 5);
    const float* fin = g_f[cur];
    float* fout = g_f[cur ^ 1];

    float acc[16];
#pragma unroll
    for (int i = 0; i < 16; i++) acc[i] = 0.0f;
    int row0 = g_rowstart[n], row1 = g_rowstart[n + 1];
#pragma unroll 2
    for (int row = row0; row < row1; row++) {
        int e = g_eid[row];
        float sv = fin[ei[e] * C + lane];
        const float* wr = g_w + (size_t)e * 384 + t * 128;
        float w0 = wr[lane] * sv;
        float w1 = wr[32 + lane] * sv;
        float w2 = wr[64 + lane] * sv;
        float w3 = wr[96 + lane] * sv;
        const float4* shp = reinterpret_cast<const float4*>(g_sh + (size_t)e * 16);
        float4 s0 = shp[0], s1 = shp[1], s2 = shp[2], s3 = shp[3];
        acc[0]  += w0;
        acc[1]  = fmaf(w1, s0.y, acc[1]);
        acc[2]  = fmaf(w1, s0.z, acc[2]);
        acc[3]  = fmaf(w1, s0.w, acc[3]);
        acc[4]  = fmaf(w2, s1.x, acc[4]);
        acc[5]  = fmaf(w2, s1.y, acc[5]);
        acc[6]  = fmaf(w2, s1.z, acc[6]);
        acc[7]  = fmaf(w2, s1.w, acc[7]);
        acc[8]  = fmaf(w2, s2.x, acc[8]);
        acc[9]  = fmaf(w3, s2.y, acc[9]);
        acc[10] = fmaf(w3, s2.z, acc[10]);
        acc[11] = fmaf(w3, s2.w, acc[11]);
        acc[12] = fmaf(w3, s3.x, acc[12]);
        acc[13] = fmaf(w3, s3.y, acc[13]);
        acc[14] = fmaf(w3, s3.z, acc[14]);
        acc[15] = fmaf(w3, s3.w, acc[15]);
    }
    float* a1 = g_agg + F_OFF1 + n * 3 * C + lane;
    a1[0] = acc[1]; a1[32] = acc[2]; a1[64] = acc[3];
    float* a2 = g_agg + F_OFF2 + n * 5 * C + lane;
    a2[0] = acc[4]; a2[32] = acc[5]; a2[64] = acc[6]; a2[96] = acc[7]; a2[128] = acc[8];
    float* a3 = g_agg + F_OFF3 + n * 7 * C + lane;
    a3[0] = acc[9]; a3[32] = acc[10]; a3[64] = acc[11]; a3[96] = acc[12];
    a3[128] = acc[13]; a3[160] = acc[14]; a3[192] = acc[15];

    float fv = fin[n * C + lane];
    float a0 = 0.0f;
#pragma unroll
    for (int c = 0; c < 32; c++) {
        a0 = fmaf(__shfl_sync(0xffffffffu, fv, c), sS0[c * 32 + lane], a0);
        a0 = fmaf(__shfl_sync(0xffffffffu, acc[0], c), sM0[c * 32 + lane], a0);
    }
    float ga = 0.0f;
#pragma unroll
    for (int c = 0; c < 32; c++)
        ga = fmaf(__shfl_sync(0xffffffffu, a0, c), sGw[c * 32 + lane], ga);
    float gate = 1.0f / (1.0f + expf(-ga));
    float s0v = siluf(a0);
    fout[n * C + lane] = s0v;
    g_gate[n * C + lane] = gate;
    if (t == 2) out[(size_t)n * 512 + lane] = s0v;
}

// ---------------- K4b: l>=1 node update as dense GEMM ----------------------
constexpr int NB1 = (3 * NNODE + 63) / 64;
constexpr int NB2 = (5 * NNODE + 63) / 64;
constexpr int NB3 = (7 * NNODE + 63) / 64;
__global__ __launch_bounds__(256) void k_nodeL(const float* __restrict__ self_w,
                                               const float* __restrict__ msg_w,
                                               int t, int cur,
                                               float* __restrict__ out) {
    __shared__ float sF[32][68];
    __shared__ float sA[32][68];
    __shared__ float sWs[32][33];
    __shared__ float sWm[32][33];
    int bid = blockIdx.x;
    int l, row0, regrows, regbase;
    if (bid < NB1)            { l = 1; row0 = bid * 64;               regrows = 3 * NNODE; regbase = F_OFF1; }
    else if (bid < NB1 + NB2) { l = 2; row0 = (bid - NB1) * 64;       regrows = 5 * NNODE; regbase = F_OFF2; }
    else                      { l = 3; row0 = (bid - NB1 - NB2) * 64; regrows = 7 * NNODE; regbase = F_OFF3; }
    int tid = threadIdx.x;
    const float* fin = g_f[cur];
    float* fout = g_f[cur ^ 1];
    for (int i = tid; i < 1024; i += 256) {
        int c = i >> 5, d = i & 31;
        sWs[c][d] = self_w[t * 4096 + l * 1024 + i];
        sWm[c][d] = msg_w [t * 4096 + l * 1024 + i];
    }
    int nrows = min(64, regrows - row0);
    {
        int trow = tid >> 2, kh = tid & 3;
        float4 z = make_float4(0.f, 0.f, 0.f, 0.f);
        float4 v0 = z, v1 = z, w0 = z, w1 = z;
        if (trow < nrows) {
            const float4* fp = reinterpret_cast<const float4*>(fin + regbase + (size_t)(row0 + trow) * 32);
            const float4* ap = reinterpret_cast<const float4*>(g_agg + regbase + (size_t)(row0 + trow) * 32);
            v0 = fp[kh]; v1 = fp[kh + 4];
            w0 = ap[kh]; w1 = ap[kh + 4];
        }
        int k0 = kh * 4;
        sF[k0][trow] = v0.x; sF[k0 + 1][trow] = v0.y; sF[k0 + 2][trow] = v0.z; sF[k0 + 3][trow] = v0.w;
        sF[k0 + 16][trow] = v1.x; sF[k0 + 17][trow] = v1.y; sF[k0 + 18][trow] = v1.z; sF[k0 + 19][trow] = v1.w;
        sA[k0][trow] = w0.x; sA[k0 + 1][trow] = w0.y; sA[k0 + 2][trow] = w0.z; sA[k0 + 3][trow] = w0.w;
        sA[k0 + 16][trow] = w1.x; sA[k0 + 17][trow] = w1.y; sA[k0 + 18][trow] = w1.z; sA[k0 + 19][trow] = w1.w;
    }
    __syncthreads();
    int col = tid & 31, rg = tid >> 5;
    ull acc[4] = {0ull, 0ull, 0ull, 0ull};
#pragma unroll
    for (int k = 0; k < 32; k++) {
        const ulonglong2* fa = reinterpret_cast<const ulonglong2*>(&sF[k][rg * 8]);
        const ulonglong2* aa = reinterpret_cast<const ulonglong2*>(&sA[k][rg * 8]);
        ulonglong2 f01 = fa[0], f23 = fa[1];
        ulonglong2 a01 = aa[0], a23 = aa[1];
        ull bs = dup2(sWs[k][col]);
        ull bm = dup2(sWm[k][col]);
        ffma2(acc[0], f01.x, bs); ffma2(acc[0], a01.x, bm);
        ffma2(acc[1], f01.y, bs); ffma2(acc[1], a01.y, bm);
        ffma2(acc[2], f23.x, bs); ffma2(acc[2], a23.x, bm);
        ffma2(acc[3], f23.y, bs); ffma2(acc[3], a23.y, bm);
    }
    int r0 = rg * 8;
#pragma unroll
    for (int p = 0; p < 4; p++) {
        float2 v = unpack2(acc[p]);
        float vv[2] = {v.x, v.y};
#pragma unroll
        for (int j = 0; j < 2; j++) {
            int lrow = r0 + 2 * p + j;
            if (lrow >= nrows) continue;
            int grow = row0 + lrow;
            int node, m;
            if (l == 1)      { node = grow / 3; m = grow - node * 3; }
            else if (l == 2) { node = grow / 5; m = grow - node * 5; }
            else             { node = grow / 7; m = grow - node * 7; }
            float res = vv[j] * g_gate[node * C + col];
            if (t < 2) {
                fout[regbase + (size_t)grow * 32 + col] = res;
            } else {
                int colb = (l == 1) ? 32 : (l == 2) ? 128 : 288;
                out[(size_t)node * 512 + colb + col * (2 * l + 1) + m] = res;
            }
        }
    }
}

// ---------------- edge output: linear, smem-staged coalesced stores --------
__global__ __launch_bounds__(256) void k_edgeout(const int* __restrict__ ei,
                                                 float* __restrict__ out, int cur) {
    __shared__ float buf[8][512];
    int lane = threadIdx.x & 31;
    int w = threadIdx.x >> 5;
    int e = blockIdx.x * 8 + w;
    int s = ei[e], d = ei[NEDGE + e];
    const float* f0 = g_f[cur];
    float gv = f0[s * C + lane] + f0[d * C + lane];
    const float* ewp = g_ew + (size_t)e * 128;
    float ew0 = ewp[lane], ew1 = ewp[32 + lane], ew2 = ewp[64 + lane], ew3 = ewp[96 + lane];
    const float4* shp = reinterpret_cast<const float4*>(g_sh + (size_t)e * 16);
    float4 s0 = shp[0], s1 = shp[1], s2 = shp[2], s3 = shp[3];
    float* base = buf[w];
    base[lane] = ew0 * gv;
    float w1 = ew1 * gv;
    float* p1 = base + 32 + lane * 3;
    p1[0] = w1 * s0.y; p1[1] = w1 * s0.z; p1[2] = w1 * s0.w;
    float w2 = ew2 * gv;
    float* p2 = base + 128 + lane * 5;
    p2[0] = w2 * s1.x; p2[1] = w2 * s1.y; p2[2] = w2 * s1.z;
    p2[3] = w2 * s1.w; p2[4] = w2 * s2.x;
    float w3 = ew3 * gv;
    float* p3 = base + 288 + lane * 7;
    p3[0] = w3 * s2.y; p3[1] = w3 * s2.z; p3[2] = w3 * s2.w;
    p3[3] = w3 * s3.x; p3[4] = w3 * s3.y; p3[5] = w3 * s3.z; p3[6] = w3 * s3.w;
    __syncwarp();
    const float4* src4 = reinterpret_cast<const float4*>(base);
    float4* dst4 = reinterpret_cast<float4*>(out + (size_t)(NNODE + e) * 512);
#pragma unroll
    for (int j = 0; j < 4; j++) dst4[lane + 32 * j] = src4[lane + 32 * j];
}

// ---------------- launch ----------------------------------------------------
extern "C" void kernel_launch(void* const* d_in, const int* in_sizes, int n_in,
                              void* d_out, int out_size) {
    const float* pos        = (const float*)d_in[0];
    const float* node_embed = (const float*)d_in[1];
    const float* rw1        = (const float*)d_in[2];
    const float* rb1        = (const float*)d_in[3];
    const float* rw2        = (const float*)d_in[4];
    const float* rb2        = (const float*)d_in[5];
    const float* self_w     = (const float*)d_in[6];
    const float* msg_w      = (const float*)d_in[7];
    const float* gate_w     = (const float*)d_in[8];
    const float* edge_w     = (const float*)d_in[9];
    const float* edge_b     = (const float*)d_in[10];
    const int*   species    = (const int*)d_in[11];
    const int*   ei         = (const int*)d_in[12];
    float* out = (float*)d_out;

    cudaFuncSetAttribute(k_gemm1hmma, cudaFuncAttributeMaxDynamicSharedMemorySize, G1_TOT);
    cudaFuncSetAttribute(k_gemm2hmma, cudaFuncAttributeMaxDynamicSharedMemorySize, S2_TOT);

    k_geom<<<NEDGE / 256, 256>>>(pos, ei);                 // 0
    k_wconv<<<160, 256>>>(rw2, edge_w, rw1);               // 1
    k_gemm1hmma<<<NEDGE / 128, 256, G1_TOT>>>(rb1);        // 2
    dim3 g2(8, NEDGE / 128);
    k_gemm2hmma<<<g2, 256, S2_TOT>>>(rb2, edge_b);         // 3  <- profiled slot
    k_zero_sort<<<(NNODE + 255) / 256, 256>>>();
    k_count<<<NEDGE / 256, 256>>>(ei);
    k_scan<<<1, 1024>>>();
    k_filleid<<<NEDGE / 256, 256>>>(ei);
    k_initf<<<FTOT / 4 / 256, 256>>>(node_embed, species);

    int cur = 0;
    for (int t = 0; t < 3; t++) {
        k_gather<<<NNODE / 8, 256>>>(self_w, msg_w, gate_w, ei, t, cur, out);
        k_nodeL<<<NB1 + NB2 + NB3, 256>>>(self_w, msg_w, t, cur, out);
        cur ^= 1;
    }

    k_edgeout<<<NEDGE / 8, 256>>>(ei, out, cur);
}

// round 14
// speedup vs baseline: 1.4140x; 1.4140x over previous
#include <cuda_runtime.h>
#include <cuda_bf16.h>
#include <math.h>
#include <stdint.h>
#include <cstdint>

typedef unsigned long long ull;

constexpr int NNODE = 10000;
constexpr int NEDGE = 160000;
constexpr int C = 32;
constexpr int H = 64;
constexpr int F_OFF1 = NNODE * C;
constexpr int F_OFF2 = 4 * NNODE * C;
constexpr int F_OFF3 = 9 * NNODE * C;
constexpr int FTOT   = 16 * NNODE * C;

// ---------------- scratch ---------------------------------------------------
__device__ __align__(16) __nv_bfloat16 g_hb_hi[(size_t)NEDGE * H];
__device__ __align__(16) __nv_bfloat16 g_hb_lo[(size_t)NEDGE * H];
__device__ __align__(16) __nv_bfloat16 g_wb_hi[512 * 64];
__device__ __align__(16) __nv_bfloat16 g_wb_lo[512 * 64];
__device__ __align__(16) __nv_bfloat16 g_w1b_hi[64 * 128];
__device__ __align__(16) __nv_bfloat16 g_w1b_lo[64 * 128];
__device__ float  g_w [(size_t)NEDGE * 384];   // sorted order
__device__ float  g_ew[(size_t)NEDGE * 128];   // sorted order
__device__ float  g_sh[(size_t)NEDGE * 16];    // sorted order
__device__ float2 g_geo[NEDGE];                // sorted order
__device__ float  g_f[2][FTOT];
__device__ float  g_agg[FTOT];
__device__ float  g_gate[NNODE * C];
__device__ int    g_cnt[NNODE];
__device__ int    g_fill[NNODE];
__device__ int    g_rowstart[NNODE + 1];
__device__ int    g_src[NEDGE];
__device__ int    g_dst[NEDGE];
__device__ int    g_orig[NEDGE];

__device__ __forceinline__ float siluf(float x) { return x / (1.0f + expf(-x)); }

__device__ __forceinline__ ull dup2(float a) {
    ull r;
    asm("mov.b64 %0, {%1, %1};" : "=l"(r) : "r"(__float_as_uint(a)));
    return r;
}
__device__ __forceinline__ void ffma2(ull& d, ull a, ull b) {
    asm("fma.rn.f32x2 %0, %1, %2, %0;" : "+l"(d) : "l"(a), "l"(b));
}
__device__ __forceinline__ float2 unpack2(ull v) {
    float2 f;
    asm("mov.b64 {%0, %1}, %2;" : "=f"(f.x), "=f"(f.y) : "l"(v));
    return f;
}
__device__ __forceinline__ uint32_t bf2u(__nv_bfloat162 v) {
    union { __nv_bfloat162 b; uint32_t u; } c;
    c.b = v;
    return c.u;
}
__device__ __forceinline__ uint32_t smem_u32(const void* p) {
    uint32_t a;
    asm("{ .reg .u64 t; cvta.to.shared.u64 t, %1; cvt.u32.u64 %0, t; }" : "=r"(a) : "l"(p));
    return a;
}
#define SWZ128(o) ((o) ^ (((o) >> 3) & 0x70))

__device__ __forceinline__ void ldm_x4(uint32_t* r, uint32_t addr) {
    asm volatile("ldmatrix.sync.aligned.m8n8.x4.shared.b16 {%0,%1,%2,%3}, [%4];"
                 : "=r"(r[0]), "=r"(r[1]), "=r"(r[2]), "=r"(r[3]) : "r"(addr));
}
__device__ __forceinline__ void mma16816(float* c, const uint32_t* a,
                                         uint32_t b0, uint32_t b1) {
    asm volatile(
        "mma.sync.aligned.m16n8k16.row.col.f32.bf16.bf16.f32 "
        "{%0,%1,%2,%3}, {%4,%5,%6,%7}, {%8,%9}, {%0,%1,%2,%3};"
        : "+f"(c[0]), "+f"(c[1]), "+f"(c[2]), "+f"(c[3])
        : "r"(a[0]), "r"(a[1]), "r"(a[2]), "r"(a[3]), "r"(b0), "r"(b1));
}

// ---------------- sorting: counting sort by dst ----------------------------
__global__ void k_zero_sort() {
    int i = blockIdx.x * 256 + threadIdx.x;
    if (i < NNODE) { g_cnt[i] = 0; g_fill[i] = 0; }
}
__global__ void k_count(const int* __restrict__ ei) {
    int e = blockIdx.x * 256 + threadIdx.x;
    atomicAdd(&g_cnt[ei[NEDGE + e]], 1);
}
__global__ void k_scan() {
    __shared__ int part[1024];
    int t = threadIdx.x;
    int base = t * 10;
    int vals[10];
    int s = 0;
#pragma unroll
    for (int i = 0; i < 10; i++) {
        int idx = base + i;
        int v = (idx < NNODE) ? g_cnt[idx] : 0;
        vals[i] = s; s += v;
    }
    part[t] = s;
    __syncthreads();
    for (int d = 1; d < 1024; d <<= 1) {
        int v = (t >= d) ? part[t - d] : 0;
        __syncthreads();
        part[t] += v;
        __syncthreads();
    }
    int off = (t == 0) ? 0 : part[t - 1];
#pragma unroll
    for (int i = 0; i < 10; i++) {
        int idx = base + i;
        if (idx < NNODE) g_rowstart[idx] = off + vals[i];
    }
    if (t == 1023) g_rowstart[NNODE] = part[1023];
}

__global__ void k_fillgeom(const float* __restrict__ pos, const int* __restrict__ ei) {
    int e = blockIdx.x * 256 + threadIdx.x;
    int s = ei[e], d = ei[NEDGE + e];
    int p = g_rowstart[d] + atomicAdd(&g_fill[d], 1);
    g_src[p] = s; g_dst[p] = d; g_orig[p] = e;
    float ax = pos[3 * s], ay = pos[3 * s + 1], az = pos[3 * s + 2];
    float bx = pos[3 * d], by = pos[3 * d + 1], bz = pos[3 * d + 2];
    float vx = bx - ax, vy = by - ay, vz = bz - az;
    float r = sqrtf(vx * vx + vy * vy + vz * vz + 1e-12f);
    float u = fminf(r * (1.0f / 5.0f), 1.0f);
    float env = 0.5f * (cospif(u) + 1.0f);
    g_geo[p] = make_float2(u, env * 0.63245553203f / r);
    float inv = 1.0f / r;
    float x = vx * inv, y = vy * inv, z = vz * inv;
    float x2 = x * x, y2 = y * y, z2 = z * z;
    float4* shp = reinterpret_cast<float4*>(g_sh + (size_t)p * 16);
    shp[0] = make_float4(1.0f, 1.7320508f * x, 1.7320508f * y, 1.7320508f * z);
    shp[1] = make_float4(3.87298335f * x * y, 3.87298335f * y * z,
                         1.11803399f * (3.0f * z2 - 1.0f), 3.87298335f * x * z);
    shp[2] = make_float4(1.93649167f * (x2 - y2),
                         2.09165007f * y * (3.0f * x2 - y2),
                         10.2469508f * x * y * z,
                         1.62018517f * y * (5.0f * z2 - 1.0f));
    shp[3] = make_float4(1.32287566f * (5.0f * z2 * z - 3.0f * z),
                         1.62018517f * x * (5.0f * z2 - 1.0f),
                         5.12347538f * z * (x2 - y2),
                         2.09165007f * x * (x2 - 3.0f * y2));
}

// ---------------- weight pre-convert ---------------------------------------
__global__ void k_wconv(const float* __restrict__ rw2,
                        const float* __restrict__ edge_w,
                        const float* __restrict__ rw1) {
    int idx = blockIdx.x * 256 + threadIdx.x;
    if (idx < 512 * 64) {
        int n = idx >> 6, k = idx & 63;
        float x = (n < 384) ? rw2[k * 384 + n] : edge_w[k * 128 + n - 384];
        __nv_bfloat16 h = __float2bfloat16_rn(x);
        g_wb_hi[idx] = h;
        g_wb_lo[idx] = __float2bfloat16_rn(x - __bfloat162float(h));
    } else {
        int j = idx - 512 * 64;
        int n = j >> 7, k = j & 127;
        float x = rw1[k * 64 + n];
        __nv_bfloat16 h = __float2bfloat16_rn(x);
        g_w1b_hi[j] = h;
        g_w1b_lo[j] = __float2bfloat16_rn(x - __bfloat162float(h));
    }
}

// ---------------- K2: h = silu(rb @ rw1 + rb1) via HMMA bf16x3 -------------
constexpr int G1_A0H = 0;
constexpr int G1_A1H = 16384;
constexpr int G1_A0L = 32768;
constexpr int G1_A1L = 49152;
constexpr int G1_B0H = 65536;
constexpr int G1_B0L = 81920;
constexpr int G1_TOT = 98304;
__global__ __launch_bounds__(256) void k_gemm1hmma(const float* __restrict__ rb1) {
    extern __shared__ char smem[];
    uint32_t sb = smem_u32(smem);
    int tid = threadIdx.x, wid = tid >> 5, lane = tid & 31;
    int e0 = blockIdx.x * 128;

    for (int idx = tid; idx < 1024; idx += 256) {
        int row = idx >> 4, ch = idx & 15;
        int toff = (ch < 8) ? 0 : 8192;
        uint32_t off = SWZ128((uint32_t)(row * 128 + (ch & 7) * 16));
        size_t gsrc = (size_t)row * 128 + ch * 8;
        *reinterpret_cast<uint4*>(smem + G1_B0H + toff + off) =
            *reinterpret_cast<const uint4*>(&g_w1b_hi[gsrc]);
        *reinterpret_cast<uint4*>(smem + G1_B0L + toff + off) =
            *reinterpret_cast<const uint4*>(&g_w1b_lo[gsrc]);
    }
    {
        int row = tid & 127, half = tid >> 7;
        float2 gg = g_geo[e0 + row];
        float s1, c1;
        sincospif(gg.x, &s1, &c1);
        float two = 2.0f * c1;
        char* tH = smem + (half ? G1_A1H : G1_A0H);
        char* tL = smem + (half ? G1_A1L : G1_A0L);
#pragma unroll
        for (int seg = 0; seg < 2; seg++) {
            int n0 = half * 64 + seg * 32 + 1;
            float sa, ca;
            sincospif((float)n0 * gg.x, &sa, &ca);
            float sbv = sa * c1 + ca * s1;
#pragma unroll
            for (int i = 0; i < 32; i += 2) {
                float v0 = gg.y * sa;
                float sn = fmaf(two, sbv, -sa); sa = sbv; sbv = sn;
                float v1 = gg.y * sa;
                sn = fmaf(two, sbv, -sa); sa = sbv; sbv = sn;
                __nv_bfloat162 h = __float22bfloat162_rn(make_float2(v0, v1));
                float2 hf = __bfloat1622float2(h);
                __nv_bfloat162 l = __float22bfloat162_rn(make_float2(v0 - hf.x, v1 - hf.y));
                uint32_t off = SWZ128((uint32_t)(row * 128 + (seg * 32 + i) * 2));
                *reinterpret_cast<uint32_t*>(tH + off) = bf2u(h);
                *reinterpret_cast<uint32_t*>(tL + off) = bf2u(l);
            }
        }
    }
    __syncthreads();

    int wr = wid & 3, wc = wid >> 2;
    int rowA0 = wr * 32 + (lane & 7) + ((lane >> 3) & 1) * 8;
    int kcA   = (lane >> 4) * 16;
    int rowB0 = wc * 32 + (lane & 7) + ((lane >> 4) & 1) * 8;
    int kcB   = ((lane >> 3) & 1) * 16;

    float acc[2][4][4];
#pragma unroll
    for (int i = 0; i < 2; i++)
#pragma unroll
        for (int j = 0; j < 4; j++)
#pragma unroll
            for (int q = 0; q < 4; q++) acc[i][j][q] = 0.0f;

    const uint32_t A_hi[2] = {sb + G1_A0H, sb + G1_A1H};
    const uint32_t A_lo[2] = {sb + G1_A0L, sb + G1_A1L};
    const uint32_t B_hi[2] = {sb + G1_B0H, sb + G1_B0H + 8192};
    const uint32_t B_lo[2] = {sb + G1_B0L, sb + G1_B0L + 8192};
#pragma unroll
    for (int p = 0; p < 3; p++) {
        const uint32_t* Ab = (p == 2) ? A_lo : A_hi;
        const uint32_t* Bb = (p == 1) ? B_lo : B_hi;
#pragma unroll
        for (int ks = 0; ks < 8; ks++) {
            int kh = ks >> 2, ksl = ks & 3;
            uint32_t a[2][4];
#pragma unroll
            for (int rt = 0; rt < 2; rt++) {
                uint32_t boff = (uint32_t)((rowA0 + rt * 16) * 128 + ksl * 32 + kcA);
                ldm_x4(a[rt], Ab[kh] + SWZ128(boff));
            }
#pragma unroll
            for (int ct2 = 0; ct2 < 2; ct2++) {
                uint32_t b[4];
                uint32_t boff = (uint32_t)((rowB0 + ct2 * 16) * 128 + ksl * 32 + kcB);
                ldm_x4(b, Bb[kh] + SWZ128(boff));
#pragma unroll
                for (int rt = 0; rt < 2; rt++) {
                    mma16816(acc[rt][2 * ct2],     a[rt], b[0], b[1]);
                    mma16816(acc[rt][2 * ct2 + 1], a[rt], b[2], b[3]);
                }
            }
        }
    }

    int lg = lane >> 2, lc = (lane & 3) * 2;
#pragma unroll
    for (int rt = 0; rt < 2; rt++) {
#pragma unroll
        for (int ct = 0; ct < 4; ct++) {
            int col = wc * 32 + ct * 8 + lc;
            float2 bv = *reinterpret_cast<const float2*>(&rb1[col]);
            int row0 = e0 + wr * 32 + rt * 16 + lg;
#pragma unroll
            for (int half = 0; half < 2; half++) {
                int row = row0 + half * 8;
                float v0 = siluf(acc[rt][ct][2 * half]     + bv.x);
                float v1 = siluf(acc[rt][ct][2 * half + 1] + bv.y);
                __nv_bfloat162 h = __float22bfloat162_rn(make_float2(v0, v1));
                float2 hf = __bfloat1622float2(h);
                __nv_bfloat162 l = __float22bfloat162_rn(make_float2(v0 - hf.x, v1 - hf.y));
                size_t base = (size_t)row * 64 + col;
                *reinterpret_cast<uint32_t*>(&g_hb_hi[base]) = bf2u(h);
                *reinterpret_cast<uint32_t*>(&g_hb_lo[base]) = bf2u(l);
            }
        }
    }
}

// ---------------- K3: HMMA bf16x3 GEMM, 128x128 tile, direct stores --------
constexpr int SM_AH  = 0;
constexpr int SM_AL  = 16384;
constexpr int SM_BH  = 32768;
constexpr int SM_BL  = 49152;
constexpr int SM_TOT = 65536;
__global__ __launch_bounds__(256) void k_gemm2hmma(const float* __restrict__ rb2,
                                                   const float* __restrict__ edge_b) {
    extern __shared__ char smem[];
    uint32_t sb = smem_u32(smem);
    int tid = threadIdx.x;
    int wid = tid >> 5, lane = tid & 31;
    int jb = blockIdx.x;
    int e0 = blockIdx.y * 128;
    int wr = wid & 3;
    int wc = wid >> 2;

    for (int idx = tid; idx < 1024; idx += 256) {
        int row = idx >> 3, ch = idx & 7;
        uint32_t off = SWZ128((uint32_t)(row * 128 + ch * 16));
        size_t ga = (size_t)(e0 + row) * 64 + ch * 8;
        *reinterpret_cast<uint4*>(smem + SM_AH + off) =
            *reinterpret_cast<const uint4*>(&g_hb_hi[ga]);
        *reinterpret_cast<uint4*>(smem + SM_AL + off) =
            *reinterpret_cast<const uint4*>(&g_hb_lo[ga]);
        size_t gb = (size_t)(jb * 128 + row) * 64 + ch * 8;
        *reinterpret_cast<uint4*>(smem + SM_BH + off) =
            *reinterpret_cast<const uint4*>(&g_wb_hi[gb]);
        *reinterpret_cast<uint4*>(smem + SM_BL + off) =
            *reinterpret_cast<const uint4*>(&g_wb_lo[gb]);
    }
    __syncthreads();

    int rowA0 = wr * 32 + (lane & 7) + ((lane >> 3) & 1) * 8;
    int kcA   = (lane >> 4) * 16;
    int rowB0 = wc * 64 + (lane & 7) + ((lane >> 4) & 1) * 8;
    int kcB   = ((lane >> 3) & 1) * 16;

    float acc[2][8][4];
#pragma unroll
    for (int i = 0; i < 2; i++)
#pragma unroll
        for (int j = 0; j < 8; j++)
#pragma unroll
            for (int q = 0; q < 4; q++) acc[i][j][q] = 0.0f;

    const uint32_t Abase[3] = {sb + SM_AH, sb + SM_AH, sb + SM_AL};
    const uint32_t Bbase[3] = {sb + SM_BH, sb + SM_BL, sb + SM_BH};
#pragma unroll
    for (int p = 0; p < 3; p++) {
        uint32_t Ab = Abase[p], Bb = Bbase[p];
#pragma unroll
        for (int ks = 0; ks < 4; ks++) {
            uint32_t a[2][4];
#pragma unroll
            for (int rt = 0; rt < 2; rt++) {
                uint32_t boff = (uint32_t)((rowA0 + rt * 16) * 128 + ks * 32 + kcA);
                ldm_x4(a[rt], Ab + SWZ128(boff));
            }
#pragma unroll
            for (int ct2 = 0; ct2 < 4; ct2++) {
                uint32_t b[4];
                uint32_t boff = (uint32_t)((rowB0 + ct2 * 16) * 128 + ks * 32 + kcB);
                ldm_x4(b, Bb + SWZ128(boff));
#pragma unroll
                for (int rt = 0; rt < 2; rt++) {
                    mma16816(acc[rt][2 * ct2],     a[rt], b[0], b[1]);
                    mma16816(acc[rt][2 * ct2 + 1], a[rt], b[2], b[3]);
                }
            }
        }
    }

    const float* bias_base = (jb < 3) ? (rb2 + jb * 128) : edge_b;
    int lg = lane >> 2;
    int lc = (lane & 3) * 2;
    int stride = (jb < 3) ? 384 : 128;
    float* gbase = (jb < 3) ? (g_w + jb * 128) : g_ew;
#pragma unroll
    for (int rt = 0; rt < 2; rt++) {
#pragma unroll
        for (int ct = 0; ct < 8; ct++) {
            int colg = wc * 64 + ct * 8 + lc;
            float2 bv = *reinterpret_cast<const float2*>(bias_base + colg);
            int row0 = e0 + wr * 32 + rt * 16 + lg;
            float* d0 = gbase + (size_t)row0 * stride + colg;
            float* d1 = gbase + (size_t)(row0 + 8) * stride + colg;
            *reinterpret_cast<float2*>(d0) =
                make_float2(acc[rt][ct][0] + bv.x, acc[rt][ct][1] + bv.y);
            *reinterpret_cast<float2*>(d1) =
                make_float2(acc[rt][ct][2] + bv.x, acc[rt][ct][3] + bv.y);
        }
    }
}

// ---------------- init f[0] -------------------------------------------------
__global__ void k_initf(const float* __restrict__ node_embed,
                        const int* __restrict__ species) {
    int i4 = blockIdx.x * 256 + threadIdx.x;
    int idx = i4 * 4;
    float4 v;
    if (idx < NNODE * C) {
        int n = idx >> 5, c = idx & 31;
        v = *reinterpret_cast<const float4*>(&node_embed[(species[n] << 5) + c]);
    } else {
        v = make_float4(0.f, 0.f, 0.f, 0.f);
    }
    *reinterpret_cast<float4*>(&g_f[0][idx]) = v;
}

// ---------------- K4a: gather-aggregate + l0 update + gate (1 warp/node) ---
__global__ __launch_bounds__(256) void k_gather(const float* __restrict__ self_w,
                                                const float* __restrict__ msg_w,
                                                const float* __restrict__ gate_w,
                                                int t, int cur,
                                                float* __restrict__ out) {
    __shared__ float sS0[1024];
    __shared__ float sM0[1024];
    __shared__ float sGw[1024];
    int tid = threadIdx.x;
    for (int i = tid; i < 1024; i += 256) {
        sS0[i] = self_w[t * 4096 + i];
        sM0[i] = msg_w[t * 4096 + i];
        sGw[i] = gate_w[t * 1024 + i];
    }
    __syncthreads();
    int lane = tid & 31;
    int n = blockIdx.x * 8 + (tid >> 5);
    const float* fin = g_f[cur];
    float* fout = g_f[cur ^ 1];

    float acc[16];
#pragma unroll
    for (int i = 0; i < 16; i++) acc[i] = 0.0f;
    int row0 = g_rowstart[n], row1 = g_rowstart[n + 1];
#pragma unroll 2
    for (int row = row0; row < row1; row++) {
        float sv = fin[g_src[row] * C + lane];
        const float* wr = g_w + (size_t)row * 384 + t * 128;
        float w0 = wr[lane] * sv;
        float w1 = wr[32 + lane] * sv;
        float w2 = wr[64 + lane] * sv;
        float w3 = wr[96 + lane] * sv;
        const float4* shp = reinterpret_cast<const float4*>(g_sh + (size_t)row * 16);
        float4 s0 = shp[0], s1 = shp[1], s2 = shp[2], s3 = shp[3];
        acc[0]  += w0;
        acc[1]  = fmaf(w1, s0.y, acc[1]);
        acc[2]  = fmaf(w1, s0.z, acc[2]);
        acc[3]  = fmaf(w1, s0.w, acc[3]);
        acc[4]  = fmaf(w2, s1.x, acc[4]);
        acc[5]  = fmaf(w2, s1.y, acc[5]);
        acc[6]  = fmaf(w2, s1.z, acc[6]);
        acc[7]  = fmaf(w2, s1.w, acc[7]);
        acc[8]  = fmaf(w2, s2.x, acc[8]);
        acc[9]  = fmaf(w3, s2.y, acc[9]);
        acc[10] = fmaf(w3, s2.z, acc[10]);
        acc[11] = fmaf(w3, s2.w, acc[11]);
        acc[12] = fmaf(w3, s3.x, acc[12]);
        acc[13] = fmaf(w3, s3.y, acc[13]);
        acc[14] = fmaf(w3, s3.z, acc[14]);
        acc[15] = fmaf(w3, s3.w, acc[15]);
    }
    float* a1 = g_agg + F_OFF1 + n * 3 * C + lane;
    a1[0] = acc[1]; a1[32] = acc[2]; a1[64] = acc[3];
    float* a2 = g_agg + F_OFF2 + n * 5 * C + lane;
    a2[0] = acc[4]; a2[32] = acc[5]; a2[64] = acc[6]; a2[96] = acc[7]; a2[128] = acc[8];
    float* a3 = g_agg + F_OFF3 + n * 7 * C + lane;
    a3[0] = acc[9]; a3[32] = acc[10]; a3[64] = acc[11]; a3[96] = acc[12];
    a3[128] = acc[13]; a3[160] = acc[14]; a3[192] = acc[15];

    float fv = fin[n * C + lane];
    float a0 = 0.0f;
#pragma unroll
    for (int c = 0; c < 32; c++) {
        a0 = fmaf(__shfl_sync(0xffffffffu, fv, c), sS0[c * 32 + lane], a0);
        a0 = fmaf(__shfl_sync(0xffffffffu, acc[0], c), sM0[c * 32 + lane], a0);
    }
    float ga = 0.0f;
#pragma unroll
    for (int c = 0; c < 32; c++)
        ga = fmaf(__shfl_sync(0xffffffffu, a0, c), sGw[c * 32 + lane], ga);
    float gate = 1.0f / (1.0f + expf(-ga));
    float s0v = siluf(a0);
    fout[n * C + lane] = s0v;
    g_gate[n * C + lane] = gate;
    if (t == 2) out[(size_t)n * 512 + lane] = s0v;
}

// ---------------- K4b: l>=1 node update as dense GEMM ----------------------
constexpr int NB1 = (3 * NNODE + 63) / 64;
constexpr int NB2 = (5 * NNODE + 63) / 64;
constexpr int NB3 = (7 * NNODE + 63) / 64;
__global__ __launch_bounds__(256) void k_nodeL(const float* __restrict__ self_w,
                                               const float* __restrict__ msg_w,
                                               int t, int cur,
                                               float* __restrict__ out) {
    __shared__ float sF[32][68];
    __shared__ float sA[32][68];
    __shared__ float sWs[32][33];
    __shared__ float sWm[32][33];
    int bid = blockIdx.x;
    int l, row0, regrows, regbase;
    if (bid < NB1)            { l = 1; row0 = bid * 64;               regrows = 3 * NNODE; regbase = F_OFF1; }
    else if (bid < NB1 + NB2) { l = 2; row0 = (bid - NB1) * 64;       regrows = 5 * NNODE; regbase = F_OFF2; }
    else                      { l = 3; row0 = (bid - NB1 - NB2) * 64; regrows = 7 * NNODE; regbase = F_OFF3; }
    int tid = threadIdx.x;
    const float* fin = g_f[cur];
    float* fout = g_f[cur ^ 1];
    for (int i = tid; i < 1024; i += 256) {
        int c = i >> 5, d = i & 31;
        sWs[c][d] = self_w[t * 4096 + l * 1024 + i];
        sWm[c][d] = msg_w [t * 4096 + l * 1024 + i];
    }
    int nrows = min(64, regrows - row0);
    {
        int trow = tid >> 2, kh = tid & 3;
        float4 z = make_float4(0.f, 0.f, 0.f, 0.f);
        float4 v0 = z, v1 = z, w0 = z, w1 = z;
        if (trow < nrows) {
            const float4* fp = reinterpret_cast<const float4*>(fin + regbase + (size_t)(row0 + trow) * 32);
            const float4* ap = reinterpret_cast<const float4*>(g_agg + regbase + (size_t)(row0 + trow) * 32);
            v0 = fp[kh]; v1 = fp[kh + 4];
            w0 = ap[kh]; w1 = ap[kh + 4];
        }
        int k0 = kh * 4;
        sF[k0][trow] = v0.x; sF[k0 + 1][trow] = v0.y; sF[k0 + 2][trow] = v0.z; sF[k0 + 3][trow] = v0.w;
        sF[k0 + 16][trow] = v1.x; sF[k0 + 17][trow] = v1.y; sF[k0 + 18][trow] = v1.z; sF[k0 + 19][trow] = v1.w;
        sA[k0][trow] = w0.x; sA[k0 + 1][trow] = w0.y; sA[k0 + 2][trow] = w0.z; sA[k0 + 3][trow] = w0.w;
        sA[k0 + 16][trow] = w1.x; sA[k0 + 17][trow] = w1.y; sA[k0 + 18][trow] = w1.z; sA[k0 + 19][trow] = w1.w;
    }
    __syncthreads();
    int col = tid & 31, rg = tid >> 5;
    ull acc[4] = {0ull, 0ull, 0ull, 0ull};
#pragma unroll
    for (int k = 0; k < 32; k++) {
        const ulonglong2* fa = reinterpret_cast<const ulonglong2*>(&sF[k][rg * 8]);
        const ulonglong2* aa = reinterpret_cast<const ulonglong2*>(&sA[k][rg * 8]);
        ulonglong2 f01 = fa[0], f23 = fa[1];
        ulonglong2 a01 = aa[0], a23 = aa[1];
        ull bs = dup2(sWs[k][col]);
        ull bm = dup2(sWm[k][col]);
        ffma2(acc[0], f01.x, bs); ffma2(acc[0], a01.x, bm);
        ffma2(acc[1], f01.y, bs); ffma2(acc[1], a01.y, bm);
        ffma2(acc[2], f23.x, bs); ffma2(acc[2], a23.x, bm);
        ffma2(acc[3], f23.y, bs); ffma2(acc[3], a23.y, bm);
    }
    int r0 = rg * 8;
#pragma unroll
    for (int p = 0; p < 4; p++) {
        float2 v = unpack2(acc[p]);
        float vv[2] = {v.x, v.y};
#pragma unroll
        for (int j = 0; j < 2; j++) {
            int lrow = r0 + 2 * p + j;
            if (lrow >= nrows) continue;
            int grow = row0 + lrow;
            int node, m;
            if (l == 1)      { node = grow / 3; m = grow - node * 3; }
            else if (l == 2) { node = grow / 5; m = grow - node * 5; }
            else             { node = grow / 7; m = grow - node * 7; }
            float res = vv[j] * g_gate[node * C + col];
            if (t < 2) {
                fout[regbase + (size_t)grow * 32 + col] = res;
            } else {
                int colb = (l == 1) ? 32 : (l == 2) ? 128 : 288;
                out[(size_t)node * 512 + colb + col * (2 * l + 1) + m] = res;
            }
        }
    }
}

// ---------------- edge output: smem-staged coalesced stores ----------------
__global__ __launch_bounds__(256) void k_edgeout(float* __restrict__ out, int cur) {
    __shared__ float buf[8][512];
    int lane = threadIdx.x & 31;
    int w = threadIdx.x >> 5;
    int e = blockIdx.x * 8 + w;
    int s = g_src[e], d = g_dst[e];
    const float* f0 = g_f[cur];
    float gv = f0[s * C + lane] + f0[d * C + lane];
    const float* ewp = g_ew + (size_t)e * 128;
    float ew0 = ewp[lane], ew1 = ewp[32 + lane], ew2 = ewp[64 + lane], ew3 = ewp[96 + lane];
    const float4* shp = reinterpret_cast<const float4*>(g_sh + (size_t)e * 16);
    float4 s0 = shp[0], s1 = shp[1], s2 = shp[2], s3 = shp[3];
    float* base = buf[w];
    base[lane] = ew0 * gv;
    float w1 = ew1 * gv;
    float* p1 = base + 32 + lane * 3;
    p1[0] = w1 * s0.y; p1[1] = w1 * s0.z; p1[2] = w1 * s0.w;
    float w2 = ew2 * gv;
    float* p2 = base + 128 + lane * 5;
    p2[0] = w2 * s1.x; p2[1] = w2 * s1.y; p2[2] = w2 * s1.z;
    p2[3] = w2 * s1.w; p2[4] = w2 * s2.x;
    float w3 = ew3 * gv;
    float* p3 = base + 288 + lane * 7;
    p3[0] = w3 * s2.y; p3[1] = w3 * s2.z; p3[2] = w3 * s2.w;
    p3[3] = w3 * s3.x; p3[4] = w3 * s3.y; p3[5] = w3 * s3.z; p3[6] = w3 * s3.w;
    __syncwarp();
    const float4* src4 = reinterpret_cast<const float4*>(base);
    float4* dst4 = reinterpret_cast<float4*>(out + (size_t)(NNODE + g_orig[e]) * 512);
#pragma unroll
    for (int j = 0; j < 4; j++) dst4[lane + 32 * j] = src4[lane + 32 * j];
}

// ---------------- launch ----------------------------------------------------
extern "C" void kernel_launch(void* const* d_in, const int* in_sizes, int n_in,
                              void* d_out, int out_size) {
    const float* pos        = (const float*)d_in[0];
    const float* node_embed = (const float*)d_in[1];
    const float* rw1        = (const float*)d_in[2];
    const float* rb1        = (const float*)d_in[3];
    const float* rw2        = (const float*)d_in[4];
    const float* rb2        = (const float*)d_in[5];
    const float* self_w     = (const float*)d_in[6];
    const float* msg_w      = (const float*)d_in[7];
    const float* gate_w     = (const float*)d_in[8];
    const float* edge_w     = (const float*)d_in[9];
    const float* edge_b     = (const float*)d_in[10];
    const int*   species    = (const int*)d_in[11];
    const int*   ei         = (const int*)d_in[12];
    float* out = (float*)d_out;

    cudaFuncSetAttribute(k_gemm1hmma, cudaFuncAttributeMaxDynamicSharedMemorySize, G1_TOT);
    cudaFuncSetAttribute(k_gemm2hmma, cudaFuncAttributeMaxDynamicSharedMemorySize, SM_TOT);

    k_zero_sort<<<(NNODE + 255) / 256, 256>>>();
    k_count<<<NEDGE / 256, 256>>>(ei);
    k_scan<<<1, 1024>>>();
    k_wconv<<<160, 256>>>(rw2, edge_w, rw1);
    k_fillgeom<<<NEDGE / 256, 256>>>(pos, ei);
    k_gemm1hmma<<<NEDGE / 128, 256, G1_TOT>>>(rb1);
    dim3 g2(4, NEDGE / 128);
    k_gemm2hmma<<<g2, 256, SM_TOT>>>(rb2, edge_b);
    k_initf<<<FTOT / 4 / 256, 256>>>(node_embed, species);

    int cur = 0;
    for (int t = 0; t < 3; t++) {
        k_gather<<<NNODE / 8, 256>>>(self_w, msg_w, gate_w, t, cur, out);
        k_nodeL<<<NB1 + NB2 + NB3, 256>>>(self_w, msg_w, t, cur, out);
        cur ^= 1;
    }

    k_edgeout<<<NEDGE / 8, 256>>>(out, cur);
}

// round 15
// speedup vs baseline: 1.4634x; 1.0349x over previous
#include <cuda_runtime.h>
#include <cuda_bf16.h>
#include <math.h>
#include <stdint.h>
#include <cstdint>

typedef unsigned long long ull;

constexpr int NNODE = 10000;
constexpr int NEDGE = 160000;
constexpr int C = 32;
constexpr int H = 64;
constexpr int F_OFF1 = NNODE * C;
constexpr int F_OFF2 = 4 * NNODE * C;
constexpr int F_OFF3 = 9 * NNODE * C;
constexpr int FTOT   = 16 * NNODE * C;

// ---------------- scratch ---------------------------------------------------
__device__ __align__(16) __nv_bfloat16 g_hb_hi[(size_t)NEDGE * H];
__device__ __align__(16) __nv_bfloat16 g_hb_lo[(size_t)NEDGE * H];
__device__ __align__(16) __nv_bfloat16 g_wb_hi[512 * 64];
__device__ __align__(16) __nv_bfloat16 g_wb_lo[512 * 64];
__device__ __align__(16) __nv_bfloat16 g_w1b_hi[64 * 128];
__device__ __align__(16) __nv_bfloat16 g_w1b_lo[64 * 128];
__device__ float  g_w [(size_t)NEDGE * 384];   // sorted order
__device__ float  g_ew[(size_t)NEDGE * 128];   // sorted order
__device__ float  g_sh[(size_t)NEDGE * 16];    // sorted order
__device__ float2 g_geo[NEDGE];                // sorted order
__device__ float  g_f[2][FTOT];
__device__ float  g_agg[FTOT];
__device__ float  g_gate[NNODE * C];
__device__ int    g_cnt[NNODE];
__device__ int    g_fill[NNODE];
__device__ int    g_rowstart[NNODE + 1];
__device__ int    g_src[NEDGE];
__device__ int    g_dst[NEDGE];
__device__ int    g_orig[NEDGE];

__device__ __forceinline__ float siluf(float x) { return x / (1.0f + expf(-x)); }

__device__ __forceinline__ ull dup2(float a) {
    ull r;
    asm("mov.b64 %0, {%1, %1};" : "=l"(r) : "r"(__float_as_uint(a)));
    return r;
}
__device__ __forceinline__ void ffma2(ull& d, ull a, ull b) {
    asm("fma.rn.f32x2 %0, %1, %2, %0;" : "+l"(d) : "l"(a), "l"(b));
}
__device__ __forceinline__ float2 unpack2(ull v) {
    float2 f;
    asm("mov.b64 {%0, %1}, %2;" : "=f"(f.x), "=f"(f.y) : "l"(v));
    return f;
}
__device__ __forceinline__ uint32_t bf2u(__nv_bfloat162 v) {
    union { __nv_bfloat162 b; uint32_t u; } c;
    c.b = v;
    return c.u;
}
__device__ __forceinline__ uint32_t smem_u32(const void* p) {
    uint32_t a;
    asm("{ .reg .u64 t; cvta.to.shared.u64 t, %1; cvt.u32.u64 %0, t; }" : "=r"(a) : "l"(p));
    return a;
}
#define SWZ128(o) ((o) ^ (((o) >> 3) & 0x70))

__device__ __forceinline__ void ldm_x4(uint32_t* r, uint32_t addr) {
    asm volatile("ldmatrix.sync.aligned.m8n8.x4.shared.b16 {%0,%1,%2,%3}, [%4];"
                 : "=r"(r[0]), "=r"(r[1]), "=r"(r[2]), "=r"(r[3]) : "r"(addr));
}
__device__ __forceinline__ void mma16816(float* c, const uint32_t* a,
                                         uint32_t b0, uint32_t b1) {
    asm volatile(
        "mma.sync.aligned.m16n8k16.row.col.f32.bf16.bf16.f32 "
        "{%0,%1,%2,%3}, {%4,%5,%6,%7}, {%8,%9}, {%0,%1,%2,%3};"
        : "+f"(c[0]), "+f"(c[1]), "+f"(c[2]), "+f"(c[3])
        : "r"(a[0]), "r"(a[1]), "r"(a[2]), "r"(a[3]), "r"(b0), "r"(b1));
}

// ---------------- sorting: counting sort by dst ----------------------------
__global__ void k_zero_sort() {
    int i = blockIdx.x * 256 + threadIdx.x;
    if (i < NNODE) { g_cnt[i] = 0; g_fill[i] = 0; }
}
__global__ void k_count(const int* __restrict__ ei) {
    int e = blockIdx.x * 256 + threadIdx.x;
    atomicAdd(&g_cnt[ei[NEDGE + e]], 1);
}
__global__ void k_scan() {
    __shared__ int part[1024];
    int t = threadIdx.x;
    int base = t * 10;
    int vals[10];
    int s = 0;
#pragma unroll
    for (int i = 0; i < 10; i++) {
        int idx = base + i;
        int v = (idx < NNODE) ? g_cnt[idx] : 0;
        vals[i] = s; s += v;
    }
    part[t] = s;
    __syncthreads();
    for (int d = 1; d < 1024; d <<= 1) {
        int v = (t >= d) ? part[t - d] : 0;
        __syncthreads();
        part[t] += v;
        __syncthreads();
    }
    int off = (t == 0) ? 0 : part[t - 1];
#pragma unroll
    for (int i = 0; i < 10; i++) {
        int idx = base + i;
        if (idx < NNODE) g_rowstart[idx] = off + vals[i];
    }
    if (t == 1023) g_rowstart[NNODE] = part[1023];
}

__global__ void k_fillgeom(const float* __restrict__ pos, const int* __restrict__ ei) {
    int e = blockIdx.x * 256 + threadIdx.x;
    int s = ei[e], d = ei[NEDGE + e];
    int p = g_rowstart[d] + atomicAdd(&g_fill[d], 1);
    g_src[p] = s; g_dst[p] = d; g_orig[p] = e;
    float ax = pos[3 * s], ay = pos[3 * s + 1], az = pos[3 * s + 2];
    float bx = pos[3 * d], by = pos[3 * d + 1], bz = pos[3 * d + 2];
    float vx = bx - ax, vy = by - ay, vz = bz - az;
    float r = sqrtf(vx * vx + vy * vy + vz * vz + 1e-12f);
    float u = fminf(r * (1.0f / 5.0f), 1.0f);
    float env = 0.5f * (cospif(u) + 1.0f);
    g_geo[p] = make_float2(u, env * 0.63245553203f / r);
    float inv = 1.0f / r;
    float x = vx * inv, y = vy * inv, z = vz * inv;
    float x2 = x * x, y2 = y * y, z2 = z * z;
    float4* shp = reinterpret_cast<float4*>(g_sh + (size_t)p * 16);
    shp[0] = make_float4(1.0f, 1.7320508f * x, 1.7320508f * y, 1.7320508f * z);
    shp[1] = make_float4(3.87298335f * x * y, 3.87298335f * y * z,
                         1.11803399f * (3.0f * z2 - 1.0f), 3.87298335f * x * z);
    shp[2] = make_float4(1.93649167f * (x2 - y2),
                         2.09165007f * y * (3.0f * x2 - y2),
                         10.2469508f * x * y * z,
                         1.62018517f * y * (5.0f * z2 - 1.0f));
    shp[3] = make_float4(1.32287566f * (5.0f * z2 * z - 3.0f * z),
                         1.62018517f * x * (5.0f * z2 - 1.0f),
                         5.12347538f * z * (x2 - y2),
                         2.09165007f * x * (x2 - 3.0f * y2));
}

// ---------------- weight pre-convert ---------------------------------------
__global__ void k_wconv(const float* __restrict__ rw2,
                        const float* __restrict__ edge_w,
                        const float* __restrict__ rw1) {
    int idx = blockIdx.x * 256 + threadIdx.x;
    if (idx < 512 * 64) {
        int n = idx >> 6, k = idx & 63;
        float x = (n < 384) ? rw2[k * 384 + n] : edge_w[k * 128 + n - 384];
        __nv_bfloat16 h = __float2bfloat16_rn(x);
        g_wb_hi[idx] = h;
        g_wb_lo[idx] = __float2bfloat16_rn(x - __bfloat162float(h));
    } else {
        int j = idx - 512 * 64;
        int n = j >> 7, k = j & 127;
        float x = rw1[k * 64 + n];
        __nv_bfloat16 h = __float2bfloat16_rn(x);
        g_w1b_hi[j] = h;
        g_w1b_lo[j] = __float2bfloat16_rn(x - __bfloat162float(h));
    }
}

// ---------------- K2: h = silu(rb @ rw1 + rb1) via HMMA bf16x3 -------------
constexpr int G1_A0H = 0;
constexpr int G1_A1H = 16384;
constexpr int G1_A0L = 32768;
constexpr int G1_A1L = 49152;
constexpr int G1_B0H = 65536;
constexpr int G1_B0L = 81920;
constexpr int G1_TOT = 98304;
__global__ __launch_bounds__(256) void k_gemm1hmma(const float* __restrict__ rb1) {
    extern __shared__ char smem[];
    uint32_t sb = smem_u32(smem);
    int tid = threadIdx.x, wid = tid >> 5, lane = tid & 31;
    int e0 = blockIdx.x * 128;

    for (int idx = tid; idx < 1024; idx += 256) {
        int row = idx >> 4, ch = idx & 15;
        int toff = (ch < 8) ? 0 : 8192;
        uint32_t off = SWZ128((uint32_t)(row * 128 + (ch & 7) * 16));
        size_t gsrc = (size_t)row * 128 + ch * 8;
        *reinterpret_cast<uint4*>(smem + G1_B0H + toff + off) =
            *reinterpret_cast<const uint4*>(&g_w1b_hi[gsrc]);
        *reinterpret_cast<uint4*>(smem + G1_B0L + toff + off) =
            *reinterpret_cast<const uint4*>(&g_w1b_lo[gsrc]);
    }
    {
        int row = tid & 127, half = tid >> 7;
        float2 gg = g_geo[e0 + row];
        float s1, c1;
        sincospif(gg.x, &s1, &c1);
        float two = 2.0f * c1;
        char* tH = smem + (half ? G1_A1H : G1_A0H);
        char* tL = smem + (half ? G1_A1L : G1_A0L);
#pragma unroll
        for (int seg = 0; seg < 2; seg++) {
            int n0 = half * 64 + seg * 32 + 1;
            float sa, ca;
            sincospif((float)n0 * gg.x, &sa, &ca);
            float sbv = sa * c1 + ca * s1;
#pragma unroll
            for (int i = 0; i < 32; i += 2) {
                float v0 = gg.y * sa;
                float sn = fmaf(two, sbv, -sa); sa = sbv; sbv = sn;
                float v1 = gg.y * sa;
                sn = fmaf(two, sbv, -sa); sa = sbv; sbv = sn;
                __nv_bfloat162 h = __float22bfloat162_rn(make_float2(v0, v1));
                float2 hf = __bfloat1622float2(h);
                __nv_bfloat162 l = __float22bfloat162_rn(make_float2(v0 - hf.x, v1 - hf.y));
                uint32_t off = SWZ128((uint32_t)(row * 128 + (seg * 32 + i) * 2));
                *reinterpret_cast<uint32_t*>(tH + off) = bf2u(h);
                *reinterpret_cast<uint32_t*>(tL + off) = bf2u(l);
            }
        }
    }
    __syncthreads();

    int wr = wid & 3, wc = wid >> 2;
    int rowA0 = wr * 32 + (lane & 7) + ((lane >> 3) & 1) * 8;
    int kcA   = (lane >> 4) * 16;
    int rowB0 = wc * 32 + (lane & 7) + ((lane >> 4) & 1) * 8;
    int kcB   = ((lane >> 3) & 1) * 16;

    float acc[2][4][4];
#pragma unroll
    for (int i = 0; i < 2; i++)
#pragma unroll
        for (int j = 0; j < 4; j++)
#pragma unroll
            for (int q = 0; q < 4; q++) acc[i][j][q] = 0.0f;

    const uint32_t A_hi[2] = {sb + G1_A0H, sb + G1_A1H};
    const uint32_t A_lo[2] = {sb + G1_A0L, sb + G1_A1L};
    const uint32_t B_hi[2] = {sb + G1_B0H, sb + G1_B0H + 8192};
    const uint32_t B_lo[2] = {sb + G1_B0L, sb + G1_B0L + 8192};
#pragma unroll
    for (int p = 0; p < 3; p++) {
        const uint32_t* Ab = (p == 2) ? A_lo : A_hi;
        const uint32_t* Bb = (p == 1) ? B_lo : B_hi;
#pragma unroll
        for (int ks = 0; ks < 8; ks++) {
            int kh = ks >> 2, ksl = ks & 3;
            uint32_t a[2][4];
#pragma unroll
            for (int rt = 0; rt < 2; rt++) {
                uint32_t boff = (uint32_t)((rowA0 + rt * 16) * 128 + ksl * 32 + kcA);
                ldm_x4(a[rt], Ab[kh] + SWZ128(boff));
            }
#pragma unroll
            for (int ct2 = 0; ct2 < 2; ct2++) {
                uint32_t b[4];
                uint32_t boff = (uint32_t)((rowB0 + ct2 * 16) * 128 + ksl * 32 + kcB);
                ldm_x4(b, Bb[kh] + SWZ128(boff));
#pragma unroll
                for (int rt = 0; rt < 2; rt++) {
                    mma16816(acc[rt][2 * ct2],     a[rt], b[0], b[1]);
                    mma16816(acc[rt][2 * ct2 + 1], a[rt], b[2], b[3]);
                }
            }
        }
    }

    int lg = lane >> 2, lc = (lane & 3) * 2;
#pragma unroll
    for (int rt = 0; rt < 2; rt++) {
#pragma unroll
        for (int ct = 0; ct < 4; ct++) {
            int col = wc * 32 + ct * 8 + lc;
            float2 bv = *reinterpret_cast<const float2*>(&rb1[col]);
            int row0 = e0 + wr * 32 + rt * 16 + lg;
#pragma unroll
            for (int half = 0; half < 2; half++) {
                int row = row0 + half * 8;
                float v0 = siluf(acc[rt][ct][2 * half]     + bv.x);
                float v1 = siluf(acc[rt][ct][2 * half + 1] + bv.y);
                __nv_bfloat162 h = __float22bfloat162_rn(make_float2(v0, v1));
                float2 hf = __bfloat1622float2(h);
                __nv_bfloat162 l = __float22bfloat162_rn(make_float2(v0 - hf.x, v1 - hf.y));
                size_t base = (size_t)row * 64 + col;
                *reinterpret_cast<uint32_t*>(&g_hb_hi[base]) = bf2u(h);
                *reinterpret_cast<uint32_t*>(&g_hb_lo[base]) = bf2u(l);
            }
        }
    }
}

// ---------------- K3: HMMA bf16x3 GEMM, 128x128 tile, 512 threads ----------
// 16 warps, warp tile 32x32 -> half the acc regs of the 256-thread version,
// double the resident warps at identical tile traffic.
constexpr int SM_AH  = 0;
constexpr int SM_AL  = 16384;
constexpr int SM_BH  = 32768;
constexpr int SM_BL  = 49152;
constexpr int SM_TOT = 65536;
__global__ __launch_bounds__(512) void k_gemm2hmma(const float* __restrict__ rb2,
                                                   const float* __restrict__ edge_b) {
    extern __shared__ char smem[];
    uint32_t sb = smem_u32(smem);
    int tid = threadIdx.x;
    int wid = tid >> 5, lane = tid & 31;
    int jb = blockIdx.x;
    int e0 = blockIdx.y * 128;
    int wr = wid & 3;         // 4 row groups x 32 rows
    int wc = wid >> 2;        // 4 col groups x 32 cols

    for (int idx = tid; idx < 1024; idx += 512) {
        int row = idx >> 3, ch = idx & 7;
        uint32_t off = SWZ128((uint32_t)(row * 128 + ch * 16));
        size_t ga = (size_t)(e0 + row) * 64 + ch * 8;
        *reinterpret_cast<uint4*>(smem + SM_AH + off) =
            *reinterpret_cast<const uint4*>(&g_hb_hi[ga]);
        *reinterpret_cast<uint4*>(smem + SM_AL + off) =
            *reinterpret_cast<const uint4*>(&g_hb_lo[ga]);
        size_t gb = (size_t)(jb * 128 + row) * 64 + ch * 8;
        *reinterpret_cast<uint4*>(smem + SM_BH + off) =
            *reinterpret_cast<const uint4*>(&g_wb_hi[gb]);
        *reinterpret_cast<uint4*>(smem + SM_BL + off) =
            *reinterpret_cast<const uint4*>(&g_wb_lo[gb]);
    }
    __syncthreads();

    int rowA0 = wr * 32 + (lane & 7) + ((lane >> 3) & 1) * 8;
    int kcA   = (lane >> 4) * 16;
    int rowB0 = wc * 32 + (lane & 7) + ((lane >> 4) & 1) * 8;
    int kcB   = ((lane >> 3) & 1) * 16;

    float acc[2][4][4];
#pragma unroll
    for (int i = 0; i < 2; i++)
#pragma unroll
        for (int j = 0; j < 4; j++)
#pragma unroll
            for (int q = 0; q < 4; q++) acc[i][j][q] = 0.0f;

    const uint32_t Abase[3] = {sb + SM_AH, sb + SM_AH, sb + SM_AL};
    const uint32_t Bbase[3] = {sb + SM_BH, sb + SM_BL, sb + SM_BH};
#pragma unroll
    for (int p = 0; p < 3; p++) {
        uint32_t Ab = Abase[p], Bb = Bbase[p];
#pragma unroll
        for (int ks = 0; ks < 4; ks++) {
            uint32_t a[2][4];
#pragma unroll
            for (int rt = 0; rt < 2; rt++) {
                uint32_t boff = (uint32_t)((rowA0 + rt * 16) * 128 + ks * 32 + kcA);
                ldm_x4(a[rt], Ab + SWZ128(boff));
            }
#pragma unroll
            for (int ct2 = 0; ct2 < 2; ct2++) {
                uint32_t b[4];
                uint32_t boff = (uint32_t)((rowB0 + ct2 * 16) * 128 + ks * 32 + kcB);
                ldm_x4(b, Bb + SWZ128(boff));
#pragma unroll
                for (int rt = 0; rt < 2; rt++) {
                    mma16816(acc[rt][2 * ct2],     a[rt], b[0], b[1]);
                    mma16816(acc[rt][2 * ct2 + 1], a[rt], b[2], b[3]);
                }
            }
        }
    }

    const float* bias_base = (jb < 3) ? (rb2 + jb * 128) : edge_b;
    int lg = lane >> 2;
    int lc = (lane & 3) * 2;
    int stride = (jb < 3) ? 384 : 128;
    float* gbase = (jb < 3) ? (g_w + jb * 128) : g_ew;
#pragma unroll
    for (int rt = 0; rt < 2; rt++) {
#pragma unroll
        for (int ct = 0; ct < 4; ct++) {
            int colg = wc * 32 + ct * 8 + lc;
            float2 bv = *reinterpret_cast<const float2*>(bias_base + colg);
            int row0 = e0 + wr * 32 + rt * 16 + lg;
            float* d0 = gbase + (size_t)row0 * stride + colg;
            float* d1 = gbase + (size_t)(row0 + 8) * stride + colg;
            *reinterpret_cast<float2*>(d0) =
                make_float2(acc[rt][ct][0] + bv.x, acc[rt][ct][1] + bv.y);
            *reinterpret_cast<float2*>(d1) =
                make_float2(acc[rt][ct][2] + bv.x, acc[rt][ct][3] + bv.y);
        }
    }
}

// ---------------- init f[0] -------------------------------------------------
__global__ void k_initf(const float* __restrict__ node_embed,
                        const int* __restrict__ species) {
    int i4 = blockIdx.x * 256 + threadIdx.x;
    int idx = i4 * 4;
    float4 v;
    if (idx < NNODE * C) {
        int n = idx >> 5, c = idx & 31;
        v = *reinterpret_cast<const float4*>(&node_embed[(species[n] << 5) + c]);
    } else {
        v = make_float4(0.f, 0.f, 0.f, 0.f);
    }
    *reinterpret_cast<float4*>(&g_f[0][idx]) = v;
}

// ---------------- K4a: gather-aggregate + l0 update + gate (1 warp/node) ---
__global__ __launch_bounds__(256) void k_gather(const float* __restrict__ self_w,
                                                const float* __restrict__ msg_w,
                                                const float* __restrict__ gate_w,
                                                int t, int cur,
                                                float* __restrict__ out) {
    __shared__ float sS0[1024];
    __shared__ float sM0[1024];
    __shared__ float sGw[1024];
    int tid = threadIdx.x;
    for (int i = tid; i < 1024; i += 256) {
        sS0[i] = self_w[t * 4096 + i];
        sM0[i] = msg_w[t * 4096 + i];
        sGw[i] = gate_w[t * 1024 + i];
    }
    __syncthreads();
    int lane = tid & 31;
    int n = blockIdx.x * 8 + (tid >> 5);
    const float* fin = g_f[cur];
    float* fout = g_f[cur ^ 1];

    float acc[16];
#pragma unroll
    for (int i = 0; i < 16; i++) acc[i] = 0.0f;
    int row0 = g_rowstart[n], row1 = g_rowstart[n + 1];
#pragma unroll 2
    for (int row = row0; row < row1; row++) {
        float sv = fin[g_src[row] * C + lane];
        const float* wr = g_w + (size_t)row * 384 + t * 128;
        float w0 = wr[lane] * sv;
        float w1 = wr[32 + lane] * sv;
        float w2 = wr[64 + lane] * sv;
        float w3 = wr[96 + lane] * sv;
        const float4* shp = reinterpret_cast<const float4*>(g_sh + (size_t)row * 16);
        float4 s0 = shp[0], s1 = shp[1], s2 = shp[2], s3 = shp[3];
        acc[0]  += w0;
        acc[1]  = fmaf(w1, s0.y, acc[1]);
        acc[2]  = fmaf(w1, s0.z, acc[2]);
        acc[3]  = fmaf(w1, s0.w, acc[3]);
        acc[4]  = fmaf(w2, s1.x, acc[4]);
        acc[5]  = fmaf(w2, s1.y, acc[5]);
        acc[6]  = fmaf(w2, s1.z, acc[6]);
        acc[7]  = fmaf(w2, s1.w, acc[7]);
        acc[8]  = fmaf(w2, s2.x, acc[8]);
        acc[9]  = fmaf(w3, s2.y, acc[9]);
        acc[10] = fmaf(w3, s2.z, acc[10]);
        acc[11] = fmaf(w3, s2.w, acc[11]);
        acc[12] = fmaf(w3, s3.x, acc[12]);
        acc[13] = fmaf(w3, s3.y, acc[13]);
        acc[14] = fmaf(w3, s3.z, acc[14]);
        acc[15] = fmaf(w3, s3.w, acc[15]);
    }
    float* a1 = g_agg + F_OFF1 + n * 3 * C + lane;
    a1[0] = acc[1]; a1[32] = acc[2]; a1[64] = acc[3];
    float* a2 = g_agg + F_OFF2 + n * 5 * C + lane;
    a2[0] = acc[4]; a2[32] = acc[5]; a2[64] = acc[6]; a2[96] = acc[7]; a2[128] = acc[8];
    float* a3 = g_agg + F_OFF3 + n * 7 * C + lane;
    a3[0] = acc[9]; a3[32] = acc[10]; a3[64] = acc[11]; a3[96] = acc[12];
    a3[128] = acc[13]; a3[160] = acc[14]; a3[192] = acc[15];

    float fv = fin[n * C + lane];
    float a0 = 0.0f;
#pragma unroll
    for (int c = 0; c < 32; c++) {
        a0 = fmaf(__shfl_sync(0xffffffffu, fv, c), sS0[c * 32 + lane], a0);
        a0 = fmaf(__shfl_sync(0xffffffffu, acc[0], c), sM0[c * 32 + lane], a0);
    }
    float ga = 0.0f;
#pragma unroll
    for (int c = 0; c < 32; c++)
        ga = fmaf(__shfl_sync(0xffffffffu, a0, c), sGw[c * 32 + lane], ga);
    float gate = 1.0f / (1.0f + expf(-ga));
    float s0v = siluf(a0);
    fout[n * C + lane] = s0v;
    g_gate[n * C + lane] = gate;
    if (t == 2) out[(size_t)n * 512 + lane] = s0v;
}

// ---------------- K4b: l>=1 node update as dense GEMM ----------------------
constexpr int NB1 = (3 * NNODE + 63) / 64;
constexpr int NB2 = (5 * NNODE + 63) / 64;
constexpr int NB3 = (7 * NNODE + 63) / 64;
__global__ __launch_bounds__(256) void k_nodeL(const float* __restrict__ self_w,
                                               const float* __restrict__ msg_w,
                                               int t, int cur,
                                               float* __restrict__ out) {
    __shared__ float sF[32][68];
    __shared__ float sA[32][68];
    __shared__ float sWs[32][33];
    __shared__ float sWm[32][33];
    int bid = blockIdx.x;
    int l, row0, regrows, regbase;
    if (bid < NB1)            { l = 1; row0 = bid * 64;               regrows = 3 * NNODE; regbase = F_OFF1; }
    else if (bid < NB1 + NB2) { l = 2; row0 = (bid - NB1) * 64;       regrows = 5 * NNODE; regbase = F_OFF2; }
    else                      { l = 3; row0 = (bid - NB1 - NB2) * 64; regrows = 7 * NNODE; regbase = F_OFF3; }
    int tid = threadIdx.x;
    const float* fin = g_f[cur];
    float* fout = g_f[cur ^ 1];
    for (int i = tid; i < 1024; i += 256) {
        int c = i >> 5, d = i & 31;
        sWs[c][d] = self_w[t * 4096 + l * 1024 + i];
        sWm[c][d] = msg_w [t * 4096 + l * 1024 + i];
    }
    int nrows = min(64, regrows - row0);
    {
        int trow = tid >> 2, kh = tid & 3;
        float4 z = make_float4(0.f, 0.f, 0.f, 0.f);
        float4 v0 = z, v1 = z, w0 = z, w1 = z;
        if (trow < nrows) {
            const float4* fp = reinterpret_cast<const float4*>(fin + regbase + (size_t)(row0 + trow) * 32);
            const float4* ap = reinterpret_cast<const float4*>(g_agg + regbase + (size_t)(row0 + trow) * 32);
            v0 = fp[kh]; v1 = fp[kh + 4];
            w0 = ap[kh]; w1 = ap[kh + 4];
        }
        int k0 = kh * 4;
        sF[k0][trow] = v0.x; sF[k0 + 1][trow] = v0.y; sF[k0 + 2][trow] = v0.z; sF[k0 + 3][trow] = v0.w;
        sF[k0 + 16][trow] = v1.x; sF[k0 + 17][trow] = v1.y; sF[k0 + 18][trow] = v1.z; sF[k0 + 19][trow] = v1.w;
        sA[k0][trow] = w0.x; sA[k0 + 1][trow] = w0.y; sA[k0 + 2][trow] = w0.z; sA[k0 + 3][trow] = w0.w;
        sA[k0 + 16][trow] = w1.x; sA[k0 + 17][trow] = w1.y; sA[k0 + 18][trow] = w1.z; sA[k0 + 19][trow] = w1.w;
    }
    __syncthreads();
    int col = tid & 31, rg = tid >> 5;
    ull acc[4] = {0ull, 0ull, 0ull, 0ull};
#pragma unroll
    for (int k = 0; k < 32; k++) {
        const ulonglong2* fa = reinterpret_cast<const ulonglong2*>(&sF[k][rg * 8]);
        const ulonglong2* aa = reinterpret_cast<const ulonglong2*>(&sA[k][rg * 8]);
        ulonglong2 f01 = fa[0], f23 = fa[1];
        ulonglong2 a01 = aa[0], a23 = aa[1];
        ull bs = dup2(sWs[k][col]);
        ull bm = dup2(sWm[k][col]);
        ffma2(acc[0], f01.x, bs); ffma2(acc[0], a01.x, bm);
        ffma2(acc[1], f01.y, bs); ffma2(acc[1], a01.y, bm);
        ffma2(acc[2], f23.x, bs); ffma2(acc[2], a23.x, bm);
        ffma2(acc[3], f23.y, bs); ffma2(acc[3], a23.y, bm);
    }
    int r0 = rg * 8;
#pragma unroll
    for (int p = 0; p < 4; p++) {
        float2 v = unpack2(acc[p]);
        float vv[2] = {v.x, v.y};
#pragma unroll
        for (int j = 0; j < 2; j++) {
            int lrow = r0 + 2 * p + j;
            if (lrow >= nrows) continue;
            int grow = row0 + lrow;
            int node, m;
            if (l == 1)      { node = grow / 3; m = grow - node * 3; }
            else if (l == 2) { node = grow / 5; m = grow - node * 5; }
            else             { node = grow / 7; m = grow - node * 7; }
            float res = vv[j] * g_gate[node * C + col];
            if (t < 2) {
                fout[regbase + (size_t)grow * 32 + col] = res;
            } else {
                int colb = (l == 1) ? 32 : (l == 2) ? 128 : 288;
                out[(size_t)node * 512 + colb + col * (2 * l + 1) + m] = res;
            }
        }
    }
}

// ---------------- edge output: smem-staged coalesced stores ----------------
__global__ __launch_bounds__(256) void k_edgeout(float* __restrict__ out, int cur) {
    __shared__ float buf[8][512];
    int lane = threadIdx.x & 31;
    int w = threadIdx.x >> 5;
    int e = blockIdx.x * 8 + w;
    int s = g_src[e], d = g_dst[e];
    const float* f0 = g_f[cur];
    float gv = f0[s * C + lane] + f0[d * C + lane];
    const float* ewp = g_ew + (size_t)e * 128;
    float ew0 = ewp[lane], ew1 = ewp[32 + lane], ew2 = ewp[64 + lane], ew3 = ewp[96 + lane];
    const float4* shp = reinterpret_cast<const float4*>(g_sh + (size_t)e * 16);
    float4 s0 = shp[0], s1 = shp[1], s2 = shp[2], s3 = shp[3];
    float* base = buf[w];
    base[lane] = ew0 * gv;
    float w1 = ew1 * gv;
    float* p1 = base + 32 + lane * 3;
    p1[0] = w1 * s0.y; p1[1] = w1 * s0.z; p1[2] = w1 * s0.w;
    float w2 = ew2 * gv;
    float* p2 = base + 128 + lane * 5;
    p2[0] = w2 * s1.x; p2[1] = w2 * s1.y; p2[2] = w2 * s1.z;
    p2[3] = w2 * s1.w; p2[4] = w2 * s2.x;
    float w3 = ew3 * gv;
    float* p3 = base + 288 + lane * 7;
    p3[0] = w3 * s2.y; p3[1] = w3 * s2.z; p3[2] = w3 * s2.w;
    p3[3] = w3 * s3.x; p3[4] = w3 * s3.y; p3[5] = w3 * s3.z; p3[6] = w3 * s3.w;
    __syncwarp();
    const float4* src4 = reinterpret_cast<const float4*>(base);
    float4* dst4 = reinterpret_cast<float4*>(out + (size_t)(NNODE + g_orig[e]) * 512);
#pragma unroll
    for (int j = 0; j < 4; j++) dst4[lane + 32 * j] = src4[lane + 32 * j];
}

// ---------------- launch ----------------------------------------------------
extern "C" void kernel_launch(void* const* d_in, const int* in_sizes, int n_in,
                              void* d_out, int out_size) {
    const float* pos        = (const float*)d_in[0];
    const float* node_embed = (const float*)d_in[1];
    const float* rw1        = (const float*)d_in[2];
    const float* rb1        = (const float*)d_in[3];
    const float* rw2        = (const float*)d_in[4];
    const float* rb2        = (const float*)d_in[5];
    const float* self_w     = (const float*)d_in[6];
    const float* msg_w      = (const float*)d_in[7];
    const float* gate_w     = (const float*)d_in[8];
    const float* edge_w     = (const float*)d_in[9];
    const float* edge_b     = (const float*)d_in[10];
    const int*   species    = (const int*)d_in[11];
    const int*   ei         = (const int*)d_in[12];
    float* out = (float*)d_out;

    cudaFuncSetAttribute(k_gemm1hmma, cudaFuncAttributeMaxDynamicSharedMemorySize, G1_TOT);
    cudaFuncSetAttribute(k_gemm2hmma, cudaFuncAttributeMaxDynamicSharedMemorySize, SM_TOT);

    k_zero_sort<<<(NNODE + 255) / 256, 256>>>();
    k_count<<<NEDGE / 256, 256>>>(ei);
    k_scan<<<1, 1024>>>();
    k_wconv<<<160, 256>>>(rw2, edge_w, rw1);
    k_fillgeom<<<NEDGE / 256, 256>>>(pos, ei);
    k_gemm1hmma<<<NEDGE / 128, 256, G1_TOT>>>(rb1);
    dim3 g2(4, NEDGE / 128);
    k_gemm2hmma<<<g2, 512, SM_TOT>>>(rb2, edge_b);
    k_initf<<<FTOT / 4 / 256, 256>>>(node_embed, species);

    int cur = 0;
    for (int t = 0; t < 3; t++) {
        k_gather<<<NNODE / 8, 256>>>(self_w, msg_w, gate_w, t, cur, out);
        k_nodeL<<<NB1 + NB2 + NB3, 256>>>(self_w, msg_w, t, cur, out);
        cur ^= 1;
    }

    k_edgeout<<<NEDGE / 8, 256>>>(out, cur);
}

// round 16
// speedup vs baseline: 1.7094x; 1.1681x over previous
#include <cuda_runtime.h>
#include <cuda_bf16.h>
#include <cuda_fp16.h>
#include <math.h>
#include <stdint.h>
#include <cstdint>

typedef unsigned long long ull;

constexpr int NNODE = 10000;
constexpr int NEDGE = 160000;
constexpr int C = 32;
constexpr int H = 64;
constexpr int F_OFF1 = NNODE * C;
constexpr int F_OFF2 = 4 * NNODE * C;
constexpr int F_OFF3 = 9 * NNODE * C;
constexpr int FTOT   = 16 * NNODE * C;

// ---------------- scratch ---------------------------------------------------
__device__ __align__(16) __half g_hf[(size_t)NEDGE * H];     // h in fp16
__device__ __align__(16) __half g_wf[512 * 64];              // [n][k] fp16 weights
__device__ __align__(16) __nv_bfloat16 g_w1b_hi[64 * 128];
__device__ __align__(16) __nv_bfloat16 g_w1b_lo[64 * 128];
__device__ float  g_w [(size_t)NEDGE * 384];   // sorted order
__device__ float  g_ew[(size_t)NEDGE * 128];   // sorted order
__device__ float  g_sh[(size_t)NEDGE * 16];    // sorted order
__device__ float2 g_geo[NEDGE];                // sorted order
__device__ float  g_f[2][FTOT];
__device__ float  g_agg[FTOT];
__device__ float  g_gate[NNODE * C];
__device__ int    g_cnt[NNODE];
__device__ int    g_fill[NNODE];
__device__ int    g_rowstart[NNODE + 1];
__device__ int    g_src[NEDGE];
__device__ int    g_dst[NEDGE];
__device__ int    g_orig[NEDGE];

__device__ __forceinline__ float siluf(float x) { return x / (1.0f + expf(-x)); }

__device__ __forceinline__ ull dup2(float a) {
    ull r;
    asm("mov.b64 %0, {%1, %1};" : "=l"(r) : "r"(__float_as_uint(a)));
    return r;
}
__device__ __forceinline__ void ffma2(ull& d, ull a, ull b) {
    asm("fma.rn.f32x2 %0, %1, %2, %0;" : "+l"(d) : "l"(a), "l"(b));
}
__device__ __forceinline__ float2 unpack2(ull v) {
    float2 f;
    asm("mov.b64 {%0, %1}, %2;" : "=f"(f.x), "=f"(f.y) : "l"(v));
    return f;
}
__device__ __forceinline__ uint32_t bf2u(__nv_bfloat162 v) {
    union { __nv_bfloat162 b; uint32_t u; } c;
    c.b = v;
    return c.u;
}
__device__ __forceinline__ uint32_t h2u(__half2 v) {
    union { __half2 h; uint32_t u; } c;
    c.h = v;
    return c.u;
}
__device__ __forceinline__ uint32_t smem_u32(const void* p) {
    uint32_t a;
    asm("{ .reg .u64 t; cvta.to.shared.u64 t, %1; cvt.u32.u64 %0, t; }" : "=r"(a) : "l"(p));
    return a;
}
#define SWZ128(o) ((o) ^ (((o) >> 3) & 0x70))

__device__ __forceinline__ void ldm_x4(uint32_t* r, uint32_t addr) {
    asm volatile("ldmatrix.sync.aligned.m8n8.x4.shared.b16 {%0,%1,%2,%3}, [%4];"
                 : "=r"(r[0]), "=r"(r[1]), "=r"(r[2]), "=r"(r[3]) : "r"(addr));
}
__device__ __forceinline__ void mma16816bf(float* c, const uint32_t* a,
                                           uint32_t b0, uint32_t b1) {
    asm volatile(
        "mma.sync.aligned.m16n8k16.row.col.f32.bf16.bf16.f32 "
        "{%0,%1,%2,%3}, {%4,%5,%6,%7}, {%8,%9}, {%0,%1,%2,%3};"
        : "+f"(c[0]), "+f"(c[1]), "+f"(c[2]), "+f"(c[3])
        : "r"(a[0]), "r"(a[1]), "r"(a[2]), "r"(a[3]), "r"(b0), "r"(b1));
}
__device__ __forceinline__ void mma16816fp(float* c, const uint32_t* a,
                                           uint32_t b0, uint32_t b1) {
    asm volatile(
        "mma.sync.aligned.m16n8k16.row.col.f32.f16.f16.f32 "
        "{%0,%1,%2,%3}, {%4,%5,%6,%7}, {%8,%9}, {%0,%1,%2,%3};"
        : "+f"(c[0]), "+f"(c[1]), "+f"(c[2]), "+f"(c[3])
        : "r"(a[0]), "r"(a[1]), "r"(a[2]), "r"(a[3]), "r"(b0), "r"(b1));
}

// ---------------- sorting: counting sort by dst ----------------------------
__global__ void k_zero_sort() {
    int i = blockIdx.x * 256 + threadIdx.x;
    if (i < NNODE) { g_cnt[i] = 0; g_fill[i] = 0; }
}
__global__ void k_count(const int* __restrict__ ei) {
    int e = blockIdx.x * 256 + threadIdx.x;
    atomicAdd(&g_cnt[ei[NEDGE + e]], 1);
}
__global__ void k_scan() {
    __shared__ int part[1024];
    int t = threadIdx.x;
    int base = t * 10;
    int vals[10];
    int s = 0;
#pragma unroll
    for (int i = 0; i < 10; i++) {
        int idx = base + i;
        int v = (idx < NNODE) ? g_cnt[idx] : 0;
        vals[i] = s; s += v;
    }
    part[t] = s;
    __syncthreads();
    for (int d = 1; d < 1024; d <<= 1) {
        int v = (t >= d) ? part[t - d] : 0;
        __syncthreads();
        part[t] += v;
        __syncthreads();
    }
    int off = (t == 0) ? 0 : part[t - 1];
#pragma unroll
    for (int i = 0; i < 10; i++) {
        int idx = base + i;
        if (idx < NNODE) g_rowstart[idx] = off + vals[i];
    }
    if (t == 1023) g_rowstart[NNODE] = part[1023];
}

__global__ void k_fillgeom(const float* __restrict__ pos, const int* __restrict__ ei) {
    int e = blockIdx.x * 256 + threadIdx.x;
    int s = ei[e], d = ei[NEDGE + e];
    int p = g_rowstart[d] + atomicAdd(&g_fill[d], 1);
    g_src[p] = s; g_dst[p] = d; g_orig[p] = e;
    float ax = pos[3 * s], ay = pos[3 * s + 1], az = pos[3 * s + 2];
    float bx = pos[3 * d], by = pos[3 * d + 1], bz = pos[3 * d + 2];
    float vx = bx - ax, vy = by - ay, vz = bz - az;
    float r = sqrtf(vx * vx + vy * vy + vz * vz + 1e-12f);
    float u = fminf(r * (1.0f / 5.0f), 1.0f);
    float env = 0.5f * (cospif(u) + 1.0f);
    g_geo[p] = make_float2(u, env * 0.63245553203f / r);
    float inv = 1.0f / r;
    float x = vx * inv, y = vy * inv, z = vz * inv;
    float x2 = x * x, y2 = y * y, z2 = z * z;
    float4* shp = reinterpret_cast<float4*>(g_sh + (size_t)p * 16);
    shp[0] = make_float4(1.0f, 1.7320508f * x, 1.7320508f * y, 1.7320508f * z);
    shp[1] = make_float4(3.87298335f * x * y, 3.87298335f * y * z,
                         1.11803399f * (3.0f * z2 - 1.0f), 3.87298335f * x * z);
    shp[2] = make_float4(1.93649167f * (x2 - y2),
                         2.09165007f * y * (3.0f * x2 - y2),
                         10.2469508f * x * y * z,
                         1.62018517f * y * (5.0f * z2 - 1.0f));
    shp[3] = make_float4(1.32287566f * (5.0f * z2 * z - 3.0f * z),
                         1.62018517f * x * (5.0f * z2 - 1.0f),
                         5.12347538f * z * (x2 - y2),
                         2.09165007f * x * (x2 - 3.0f * y2));
}

// ---------------- weight pre-convert ---------------------------------------
__global__ void k_wconv(const float* __restrict__ rw2,
                        const float* __restrict__ edge_w,
                        const float* __restrict__ rw1) {
    int idx = blockIdx.x * 256 + threadIdx.x;
    if (idx < 512 * 64) {
        int n = idx >> 6, k = idx & 63;
        float x = (n < 384) ? rw2[k * 384 + n] : edge_w[k * 128 + n - 384];
        g_wf[idx] = __float2half_rn(x);
    } else {
        int j = idx - 512 * 64;
        int n = j >> 7, k = j & 127;
        float x = rw1[k * 64 + n];
        __nv_bfloat16 h = __float2bfloat16_rn(x);
        g_w1b_hi[j] = h;
        g_w1b_lo[j] = __float2bfloat16_rn(x - __bfloat162float(h));
    }
}

// ---------------- K2: h = silu(rb @ rw1 + rb1) via HMMA bf16x3, fp16 out ---
constexpr int G1_A0H = 0;
constexpr int G1_A1H = 16384;
constexpr int G1_A0L = 32768;
constexpr int G1_A1L = 49152;
constexpr int G1_B0H = 65536;
constexpr int G1_B0L = 81920;
constexpr int G1_TOT = 98304;
__global__ __launch_bounds__(256) void k_gemm1hmma(const float* __restrict__ rb1) {
    extern __shared__ char smem[];
    uint32_t sb = smem_u32(smem);
    int tid = threadIdx.x, wid = tid >> 5, lane = tid & 31;
    int e0 = blockIdx.x * 128;

    for (int idx = tid; idx < 1024; idx += 256) {
        int row = idx >> 4, ch = idx & 15;
        int toff = (ch < 8) ? 0 : 8192;
        uint32_t off = SWZ128((uint32_t)(row * 128 + (ch & 7) * 16));
        size_t gsrc = (size_t)row * 128 + ch * 8;
        *reinterpret_cast<uint4*>(smem + G1_B0H + toff + off) =
            *reinterpret_cast<const uint4*>(&g_w1b_hi[gsrc]);
        *reinterpret_cast<uint4*>(smem + G1_B0L + toff + off) =
            *reinterpret_cast<const uint4*>(&g_w1b_lo[gsrc]);
    }
    {
        int row = tid & 127, half = tid >> 7;
        float2 gg = g_geo[e0 + row];
        float s1, c1;
        sincospif(gg.x, &s1, &c1);
        float two = 2.0f * c1;
        char* tH = smem + (half ? G1_A1H : G1_A0H);
        char* tL = smem + (half ? G1_A1L : G1_A0L);
#pragma unroll
        for (int seg = 0; seg < 2; seg++) {
            int n0 = half * 64 + seg * 32 + 1;
            float sa, ca;
            sincospif((float)n0 * gg.x, &sa, &ca);
            float sbv = sa * c1 + ca * s1;
#pragma unroll
            for (int i = 0; i < 32; i += 2) {
                float v0 = gg.y * sa;
                float sn = fmaf(two, sbv, -sa); sa = sbv; sbv = sn;
                float v1 = gg.y * sa;
                sn = fmaf(two, sbv, -sa); sa = sbv; sbv = sn;
                __nv_bfloat162 h = __float22bfloat162_rn(make_float2(v0, v1));
                float2 hf = __bfloat1622float2(h);
                __nv_bfloat162 l = __float22bfloat162_rn(make_float2(v0 - hf.x, v1 - hf.y));
                uint32_t off = SWZ128((uint32_t)(row * 128 + (seg * 32 + i) * 2));
                *reinterpret_cast<uint32_t*>(tH + off) = bf2u(h);
                *reinterpret_cast<uint32_t*>(tL + off) = bf2u(l);
            }
        }
    }
    __syncthreads();

    int wr = wid & 3, wc = wid >> 2;
    int rowA0 = wr * 32 + (lane & 7) + ((lane >> 3) & 1) * 8;
    int kcA   = (lane >> 4) * 16;
    int rowB0 = wc * 32 + (lane & 7) + ((lane >> 4) & 1) * 8;
    int kcB   = ((lane >> 3) & 1) * 16;

    float acc[2][4][4];
#pragma unroll
    for (int i = 0; i < 2; i++)
#pragma unroll
        for (int j = 0; j < 4; j++)
#pragma unroll
            for (int q = 0; q < 4; q++) acc[i][j][q] = 0.0f;

    const uint32_t A_hi[2] = {sb + G1_A0H, sb + G1_A1H};
    const uint32_t A_lo[2] = {sb + G1_A0L, sb + G1_A1L};
    const uint32_t B_hi[2] = {sb + G1_B0H, sb + G1_B0H + 8192};
    const uint32_t B_lo[2] = {sb + G1_B0L, sb + G1_B0L + 8192};
#pragma unroll
    for (int p = 0; p < 3; p++) {
        const uint32_t* Ab = (p == 2) ? A_lo : A_hi;
        const uint32_t* Bb = (p == 1) ? B_lo : B_hi;
#pragma unroll
        for (int ks = 0; ks < 8; ks++) {
            int kh = ks >> 2, ksl = ks & 3;
            uint32_t a[2][4];
#pragma unroll
            for (int rt = 0; rt < 2; rt++) {
                uint32_t boff = (uint32_t)((rowA0 + rt * 16) * 128 + ksl * 32 + kcA);
                ldm_x4(a[rt], Ab[kh] + SWZ128(boff));
            }
#pragma unroll
            for (int ct2 = 0; ct2 < 2; ct2++) {
                uint32_t b[4];
                uint32_t boff = (uint32_t)((rowB0 + ct2 * 16) * 128 + ksl * 32 + kcB);
                ldm_x4(b, Bb[kh] + SWZ128(boff));
#pragma unroll
                for (int rt = 0; rt < 2; rt++) {
                    mma16816bf(acc[rt][2 * ct2],     a[rt], b[0], b[1]);
                    mma16816bf(acc[rt][2 * ct2 + 1], a[rt], b[2], b[3]);
                }
            }
        }
    }

    int lg = lane >> 2, lc = (lane & 3) * 2;
#pragma unroll
    for (int rt = 0; rt < 2; rt++) {
#pragma unroll
        for (int ct = 0; ct < 4; ct++) {
            int col = wc * 32 + ct * 8 + lc;
            float2 bv = *reinterpret_cast<const float2*>(&rb1[col]);
            int row0 = e0 + wr * 32 + rt * 16 + lg;
#pragma unroll
            for (int half = 0; half < 2; half++) {
                int row = row0 + half * 8;
                float v0 = siluf(acc[rt][ct][2 * half]     + bv.x);
                float v1 = siluf(acc[rt][ct][2 * half + 1] + bv.y);
                __half2 hv = __floats2half2_rn(v0, v1);
                *reinterpret_cast<uint32_t*>(&g_hf[(size_t)row * 64 + col]) = h2u(hv);
            }
        }
    }
}

// ---------------- K3: fp16 single-pass HMMA GEMM, 128x128 tile, 512 thr ----
constexpr int SM_A  = 0;
constexpr int SM_B  = 16384;
constexpr int SM2_TOT = 32768;
__global__ __launch_bounds__(512, 2) void k_gemm2hmma(const float* __restrict__ rb2,
                                                      const float* __restrict__ edge_b) {
    extern __shared__ char smem[];
    uint32_t sb = smem_u32(smem);
    int tid = threadIdx.x;
    int wid = tid >> 5, lane = tid & 31;
    int jb = blockIdx.x;
    int e0 = blockIdx.y * 128;
    int wr = wid & 3;
    int wc = wid >> 2;

    for (int idx = tid; idx < 1024; idx += 512) {
        int row = idx >> 3, ch = idx & 7;
        uint32_t off = SWZ128((uint32_t)(row * 128 + ch * 16));
        *reinterpret_cast<uint4*>(smem + SM_A + off) =
            *reinterpret_cast<const uint4*>(&g_hf[(size_t)(e0 + row) * 64 + ch * 8]);
        *reinterpret_cast<uint4*>(smem + SM_B + off) =
            *reinterpret_cast<const uint4*>(&g_wf[(size_t)(jb * 128 + row) * 64 + ch * 8]);
    }
    __syncthreads();

    int rowA0 = wr * 32 + (lane & 7) + ((lane >> 3) & 1) * 8;
    int kcA   = (lane >> 4) * 16;
    int rowB0 = wc * 32 + (lane & 7) + ((lane >> 4) & 1) * 8;
    int kcB   = ((lane >> 3) & 1) * 16;

    float acc[2][4][4];
#pragma unroll
    for (int i = 0; i < 2; i++)
#pragma unroll
        for (int j = 0; j < 4; j++)
#pragma unroll
            for (int q = 0; q < 4; q++) acc[i][j][q] = 0.0f;

#pragma unroll
    for (int ks = 0; ks < 4; ks++) {
        uint32_t a[2][4];
#pragma unroll
        for (int rt = 0; rt < 2; rt++) {
            uint32_t boff = (uint32_t)((rowA0 + rt * 16) * 128 + ks * 32 + kcA);
            ldm_x4(a[rt], sb + SM_A + SWZ128(boff));
        }
#pragma unroll
        for (int ct2 = 0; ct2 < 2; ct2++) {
            uint32_t b[4];
            uint32_t boff = (uint32_t)((rowB0 + ct2 * 16) * 128 + ks * 32 + kcB);
            ldm_x4(b, sb + SM_B + SWZ128(boff));
#pragma unroll
            for (int rt = 0; rt < 2; rt++) {
                mma16816fp(acc[rt][2 * ct2],     a[rt], b[0], b[1]);
                mma16816fp(acc[rt][2 * ct2 + 1], a[rt], b[2], b[3]);
            }
        }
    }

    const float* bias_base = (jb < 3) ? (rb2 + jb * 128) : edge_b;
    int lg = lane >> 2;
    int lc = (lane & 3) * 2;
    int stride = (jb < 3) ? 384 : 128;
    float* gbase = (jb < 3) ? (g_w + jb * 128) : g_ew;
#pragma unroll
    for (int rt = 0; rt < 2; rt++) {
#pragma unroll
        for (int ct = 0; ct < 4; ct++) {
            int colg = wc * 32 + ct * 8 + lc;
            float2 bv = *reinterpret_cast<const float2*>(bias_base + colg);
            int row0 = e0 + wr * 32 + rt * 16 + lg;
            float* d0 = gbase + (size_t)row0 * stride + colg;
            float* d1 = gbase + (size_t)(row0 + 8) * stride + colg;
            *reinterpret_cast<float2*>(d0) =
                make_float2(acc[rt][ct][0] + bv.x, acc[rt][ct][1] + bv.y);
            *reinterpret_cast<float2*>(d1) =
                make_float2(acc[rt][ct][2] + bv.x, acc[rt][ct][3] + bv.y);
        }
    }
}

// ---------------- init f[0] -------------------------------------------------
__global__ void k_initf(const float* __restrict__ node_embed,
                        const int* __restrict__ species) {
    int i4 = blockIdx.x * 256 + threadIdx.x;
    int idx = i4 * 4;
    float4 v;
    if (idx < NNODE * C) {
        int n = idx >> 5, c = idx & 31;
        v = *reinterpret_cast<const float4*>(&node_embed[(species[n] << 5) + c]);
    } else {
        v = make_float4(0.f, 0.f, 0.f, 0.f);
    }
    *reinterpret_cast<float4*>(&g_f[0][idx]) = v;
}

// ---------------- K4a: gather-aggregate + l0 update + gate (1 warp/node) ---
__global__ __launch_bounds__(256) void k_gather(const float* __restrict__ self_w,
                                                const float* __restrict__ msg_w,
                                                const float* __restrict__ gate_w,
                                                int t, int cur,
                                                float* __restrict__ out) {
    __shared__ float sS0[1024];
    __shared__ float sM0[1024];
    __shared__ float sGw[1024];
    int tid = threadIdx.x;
    for (int i = tid; i < 1024; i += 256) {
        sS0[i] = self_w[t * 4096 + i];
        sM0[i] = msg_w[t * 4096 + i];
        sGw[i] = gate_w[t * 1024 + i];
    }
    __syncthreads();
    int lane = tid & 31;
    int n = blockIdx.x * 8 + (tid >> 5);
    const float* fin = g_f[cur];
    float* fout = g_f[cur ^ 1];

    float acc[16];
#pragma unroll
    for (int i = 0; i < 16; i++) acc[i] = 0.0f;
    int row0 = g_rowstart[n], row1 = g_rowstart[n + 1];
#pragma unroll 2
    for (int row = row0; row < row1; row++) {
        float sv = fin[g_src[row] * C + lane];
        const float* wr = g_w + (size_t)row * 384 + t * 128;
        float w0 = wr[lane] * sv;
        float w1 = wr[32 + lane] * sv;
        float w2 = wr[64 + lane] * sv;
        float w3 = wr[96 + lane] * sv;
        const float4* shp = reinterpret_cast<const float4*>(g_sh + (size_t)row * 16);
        float4 s0 = shp[0], s1 = shp[1], s2 = shp[2], s3 = shp[3];
        acc[0]  += w0;
        acc[1]  = fmaf(w1, s0.y, acc[1]);
        acc[2]  = fmaf(w1, s0.z, acc[2]);
        acc[3]  = fmaf(w1, s0.w, acc[3]);
        acc[4]  = fmaf(w2, s1.x, acc[4]);
        acc[5]  = fmaf(w2, s1.y, acc[5]);
        acc[6]  = fmaf(w2, s1.z, acc[6]);
        acc[7]  = fmaf(w2, s1.w, acc[7]);
        acc[8]  = fmaf(w2, s2.x, acc[8]);
        acc[9]  = fmaf(w3, s2.y, acc[9]);
        acc[10] = fmaf(w3, s2.z, acc[10]);
        acc[11] = fmaf(w3, s2.w, acc[11]);
        acc[12] = fmaf(w3, s3.x, acc[12]);
        acc[13] = fmaf(w3, s3.y, acc[13]);
        acc[14] = fmaf(w3, s3.z, acc[14]);
        acc[15] = fmaf(w3, s3.w, acc[15]);
    }
    float* a1 = g_agg + F_OFF1 + n * 3 * C + lane;
    a1[0] = acc[1]; a1[32] = acc[2]; a1[64] = acc[3];
    float* a2 = g_agg + F_OFF2 + n * 5 * C + lane;
    a2[0] = acc[4]; a2[32] = acc[5]; a2[64] = acc[6]; a2[96] = acc[7]; a2[128] = acc[8];
    float* a3 = g_agg + F_OFF3 + n * 7 * C + lane;
    a3[0] = acc[9]; a3[32] = acc[10]; a3[64] = acc[11]; a3[96] = acc[12];
    a3[128] = acc[13]; a3[160] = acc[14]; a3[192] = acc[15];

    float fv = fin[n * C + lane];
    float a0 = 0.0f;
#pragma unroll
    for (int c = 0; c < 32; c++) {
        a0 = fmaf(__shfl_sync(0xffffffffu, fv, c), sS0[c * 32 + lane], a0);
        a0 = fmaf(__shfl_sync(0xffffffffu, acc[0], c), sM0[c * 32 + lane], a0);
    }
    float ga = 0.0f;
#pragma unroll
    for (int c = 0; c < 32; c++)
        ga = fmaf(__shfl_sync(0xffffffffu, a0, c), sGw[c * 32 + lane], ga);
    float gate = 1.0f / (1.0f + expf(-ga));
    float s0v = siluf(a0);
    fout[n * C + lane] = s0v;
    g_gate[n * C + lane] = gate;
    if (t == 2) out[(size_t)n * 512 + lane] = s0v;
}

// ---------------- K4b: l>=1 node update as dense GEMM ----------------------
constexpr int NB1 = (3 * NNODE + 63) / 64;
constexpr int NB2 = (5 * NNODE + 63) / 64;
constexpr int NB3 = (7 * NNODE + 63) / 64;
__global__ __launch_bounds__(256) void k_nodeL(const float* __restrict__ self_w,
                                               const float* __restrict__ msg_w,
                                               int t, int cur,
                                               float* __restrict__ out) {
    __shared__ float sF[32][68];
    __shared__ float sA[32][68];
    __shared__ float sWs[32][33];
    __shared__ float sWm[32][33];
    int bid = blockIdx.x;
    int l, row0, regrows, regbase;
    if (bid < NB1)            { l = 1; row0 = bid * 64;               regrows = 3 * NNODE; regbase = F_OFF1; }
    else if (bid < NB1 + NB2) { l = 2; row0 = (bid - NB1) * 64;       regrows = 5 * NNODE; regbase = F_OFF2; }
    else                      { l = 3; row0 = (bid - NB1 - NB2) * 64; regrows = 7 * NNODE; regbase = F_OFF3; }
    int tid = threadIdx.x;
    const float* fin = g_f[cur];
    float* fout = g_f[cur ^ 1];
    for (int i = tid; i < 1024; i += 256) {
        int c = i >> 5, d = i & 31;
        sWs[c][d] = self_w[t * 4096 + l * 1024 + i];
        sWm[c][d] = msg_w [t * 4096 + l * 1024 + i];
    }
    int nrows = min(64, regrows - row0);
    {
        int trow = tid >> 2, kh = tid & 3;
        float4 z = make_float4(0.f, 0.f, 0.f, 0.f);
        float4 v0 = z, v1 = z, w0 = z, w1 = z;
        if (trow < nrows) {
            const float4* fp = reinterpret_cast<const float4*>(fin + regbase + (size_t)(row0 + trow) * 32);
            const float4* ap = reinterpret_cast<const float4*>(g_agg + regbase + (size_t)(row0 + trow) * 32);
            v0 = fp[kh]; v1 = fp[kh + 4];
            w0 = ap[kh]; w1 = ap[kh + 4];
        }
        int k0 = kh * 4;
        sF[k0][trow] = v0.x; sF[k0 + 1][trow] = v0.y; sF[k0 + 2][trow] = v0.z; sF[k0 + 3][trow] = v0.w;
        sF[k0 + 16][trow] = v1.x; sF[k0 + 17][trow] = v1.y; sF[k0 + 18][trow] = v1.z; sF[k0 + 19][trow] = v1.w;
        sA[k0][trow] = w0.x; sA[k0 + 1][trow] = w0.y; sA[k0 + 2][trow] = w0.z; sA[k0 + 3][trow] = w0.w;
        sA[k0 + 16][trow] = w1.x; sA[k0 + 17][trow] = w1.y; sA[k0 + 18][trow] = w1.z; sA[k0 + 19][trow] = w1.w;
    }
    __syncthreads();
    int col = tid & 31, rg = tid >> 5;
    ull acc[4] = {0ull, 0ull, 0ull, 0ull};
#pragma unroll
    for (int k = 0; k < 32; k++) {
        const ulonglong2* fa = reinterpret_cast<const ulonglong2*>(&sF[k][rg * 8]);
        const ulonglong2* aa = reinterpret_cast<const ulonglong2*>(&sA[k][rg * 8]);
        ulonglong2 f01 = fa[0], f23 = fa[1];
        ulonglong2 a01 = aa[0], a23 = aa[1];
        ull bs = dup2(sWs[k][col]);
        ull bm = dup2(sWm[k][col]);
        ffma2(acc[0], f01.x, bs); ffma2(acc[0], a01.x, bm);
        ffma2(acc[1], f01.y, bs); ffma2(acc[1], a01.y, bm);
        ffma2(acc[2], f23.x, bs); ffma2(acc[2], a23.x, bm);
        ffma2(acc[3], f23.y, bs); ffma2(acc[3], a23.y, bm);
    }
    int r0 = rg * 8;
#pragma unroll
    for (int p = 0; p < 4; p++) {
        float2 v = unpack2(acc[p]);
        float vv[2] = {v.x, v.y};
#pragma unroll
        for (int j = 0; j < 2; j++) {
            int lrow = r0 + 2 * p + j;
            if (lrow >= nrows) continue;
            int grow = row0 + lrow;
            int node, m;
            if (l == 1)      { node = grow / 3; m = grow - node * 3; }
            else if (l == 2) { node = grow / 5; m = grow - node * 5; }
            else             { node = grow / 7; m = grow - node * 7; }
            float res = vv[j] * g_gate[node * C + col];
            if (t < 2) {
                fout[regbase + (size_t)grow * 32 + col] = res;
            } else {
                int colb = (l == 1) ? 32 : (l == 2) ? 128 : 288;
                out[(size_t)node * 512 + colb + col * (2 * l + 1) + m] = res;
            }
        }
    }
}

// ---------------- edge output: smem-staged coalesced stores ----------------
__global__ __launch_bounds__(256) void k_edgeout(float* __restrict__ out, int cur) {
    __shared__ float buf[8][512];
    int lane = threadIdx.x & 31;
    int w = threadIdx.x >> 5;
    int e = blockIdx.x * 8 + w;
    int s = g_src[e], d = g_dst[e];
    const float* f0 = g_f[cur];
    float gv = f0[s * C + lane] + f0[d * C + lane];
    const float* ewp = g_ew + (size_t)e * 128;
    float ew0 = ewp[lane], ew1 = ewp[32 + lane], ew2 = ewp[64 + lane], ew3 = ewp[96 + lane];
    const float4* shp = reinterpret_cast<const float4*>(g_sh + (size_t)e * 16);
    float4 s0 = shp[0], s1 = shp[1], s2 = shp[2], s3 = shp[3];
    float* base = buf[w];
    base[lane] = ew0 * gv;
    float w1 = ew1 * gv;
    float* p1 = base + 32 + lane * 3;
    p1[0] = w1 * s0.y; p1[1] = w1 * s0.z; p1[2] = w1 * s0.w;
    float w2 = ew2 * gv;
    float* p2 = base + 128 + lane * 5;
    p2[0] = w2 * s1.x; p2[1] = w2 * s1.y; p2[2] = w2 * s1.z;
    p2[3] = w2 * s1.w; p2[4] = w2 * s2.x;
    float w3 = ew3 * gv;
    float* p3 = base + 288 + lane * 7;
    p3[0] = w3 * s2.y; p3[1] = w3 * s2.z; p3[2] = w3 * s2.w;
    p3[3] = w3 * s3.x; p3[4] = w3 * s3.y; p3[5] = w3 * s3.z; p3[6] = w3 * s3.w;
    __syncwarp();
    const float4* src4 = reinterpret_cast<const float4*>(base);
    float4* dst4 = reinterpret_cast<float4*>(out + (size_t)(NNODE + g_orig[e]) * 512);
#pragma unroll
    for (int j = 0; j < 4; j++) dst4[lane + 32 * j] = src4[lane + 32 * j];
}

// ---------------- launch ----------------------------------------------------
extern "C" void kernel_launch(void* const* d_in, const int* in_sizes, int n_in,
                              void* d_out, int out_size) {
    const float* pos        = (const float*)d_in[0];
    const float* node_embed = (const float*)d_in[1];
    const float* rw1        = (const float*)d_in[2];
    const float* rb1        = (const float*)d_in[3];
    const float* rw2        = (const float*)d_in[4];
    const float* rb2        = (const float*)d_in[5];
    const float* self_w     = (const float*)d_in[6];
    const float* msg_w      = (const float*)d_in[7];
    const float* gate_w     = (const float*)d_in[8];
    const float* edge_w     = (const float*)d_in[9];
    const float* edge_b     = (const float*)d_in[10];
    const int*   species    = (const int*)d_in[11];
    const int*   ei         = (const int*)d_in[12];
    float* out = (float*)d_out;

    cudaFuncSetAttribute(k_gemm1hmma, cudaFuncAttributeMaxDynamicSharedMemorySize, G1_TOT);
    cudaFuncSetAttribute(k_gemm2hmma, cudaFuncAttributeMaxDynamicSharedMemorySize, SM2_TOT);

    k_zero_sort<<<(NNODE + 255) / 256, 256>>>();
    k_count<<<NEDGE / 256, 256>>>(ei);
    k_scan<<<1, 1024>>>();
    k_wconv<<<160, 256>>>(rw2, edge_w, rw1);
    k_fillgeom<<<NEDGE / 256, 256>>>(pos, ei);
    k_gemm1hmma<<<NEDGE / 128, 256, G1_TOT>>>(rb1);
    dim3 g2(4, NEDGE / 128);
    k_gemm2hmma<<<g2, 512, SM2_TOT>>>(rb2, edge_b);
    k_initf<<<FTOT / 4 / 256, 256>>>(node_embed, species);

    int cur = 0;
    for (int t = 0; t < 3; t++) {
        k_gather<<<NNODE / 8, 256>>>(self_w, msg_w, gate_w, t, cur, out);
        k_nodeL<<<NB1 + NB2 + NB3, 256>>>(self_w, msg_w, t, cur, out);
        cur ^= 1;
    }

    k_edgeout<<<NEDGE / 8, 256>>>(out, cur);
}